// round 1
// baseline (speedup 1.0000x reference)
#include <cuda_runtime.h>
#include <math.h>

// ---------------------------------------------------------------------------
// SelectiveStateSpace: B=8, S=2048, D_MODEL=1024, N=64
//   Pass 1 (proj_kernel):  P = X @ Wcat^T ; delta=softplus, u=Bt*x[:, :64], C
//   Pass 2 (recur_kernel): warp-per-(b,i) sequential scan over t
// ---------------------------------------------------------------------------

#define BQ   8
#define SQ   2048
#define DM   1024
#define NS   64
#define ROWS (BQ * SQ)        // 16384

// scratch (device globals; no allocation allowed)
__device__ float g_delta[ROWS * NS];
__device__ float g_u[ROWS * NS];
__device__ float g_c[ROWS * NS];

// ------------------------------- f32x2 helpers ------------------------------
__device__ __forceinline__ unsigned long long pk2(float lo, float hi) {
    unsigned long long r;
    asm("mov.b64 %0, {%1, %2};" : "=l"(r) : "f"(lo), "f"(hi));
    return r;
}
__device__ __forceinline__ void fma2(unsigned long long& d, unsigned long long a,
                                     unsigned long long b) {
    asm("fma.rn.f32x2 %0, %1, %2, %0;" : "+l"(d) : "l"(a), "l"(b));
}
__device__ __forceinline__ float2 upk2(unsigned long long v) {
    float2 f;
    asm("mov.b64 {%0, %1}, %2;" : "=f"(f.x), "=f"(f.y) : "l"(v));
    return f;
}

__device__ __forceinline__ float softplus_f(float v) {
    return (v > 20.0f) ? v : log1pf(expf(v));
}

// ------------------------------ projection GEMM -----------------------------
// BM=128 rows, BN=192 cols (delta|Bp|Cp), BK=16, 256 threads, thread tile 8x12.
#define BM 128
#define BN 192
#define BKK 16

__global__ void __launch_bounds__(256, 1)
proj_kernel(const float* __restrict__ x,
            const float* __restrict__ Wd, const float* __restrict__ bd,
            const float* __restrict__ Wb, const float* __restrict__ bb,
            const float* __restrict__ Wc, const float* __restrict__ bc) {
    __shared__ float Xs[2][BKK][BM];
    __shared__ float Ws[2][BKK][BN];

    const int tid = threadIdx.x;
    const int tx  = tid & 15;    // n-tile
    const int ty  = tid >> 4;    // m-tile
    const int m0  = blockIdx.x * BM;

    unsigned long long acc[8][6];
#pragma unroll
    for (int r = 0; r < 8; r++)
#pragma unroll
        for (int p = 0; p < 6; p++) acc[r][p] = 0ull;

    float4 xr[2], wr[3];

    // ---- load tile kt=0 into regs ----
#pragma unroll
    for (int q = 0; q < 2; q++) {
        int idx = tid + q * 256;          // 0..511
        int row = idx >> 2, kq = idx & 3;
        xr[q] = *(const float4*)(x + (size_t)(m0 + row) * DM + kq * 4);
    }
#pragma unroll
    for (int q = 0; q < 3; q++) {
        int idx = tid + q * 256;          // 0..767
        int n = idx >> 2, kq = idx & 3;
        const float* src = (n < 64) ? Wd : ((n < 128) ? Wb : Wc);
        wr[q] = *(const float4*)(src + (size_t)(n & 63) * DM + kq * 4);
    }
    // ---- STS tile 0 ----
#pragma unroll
    for (int q = 0; q < 2; q++) {
        int idx = tid + q * 256;
        int row = idx >> 2, kq = idx & 3;
        Xs[0][kq * 4 + 0][row] = xr[q].x;
        Xs[0][kq * 4 + 1][row] = xr[q].y;
        Xs[0][kq * 4 + 2][row] = xr[q].z;
        Xs[0][kq * 4 + 3][row] = xr[q].w;
    }
#pragma unroll
    for (int q = 0; q < 3; q++) {
        int idx = tid + q * 256;
        int n = idx >> 2, kq = idx & 3;
        Ws[0][kq * 4 + 0][n] = wr[q].x;
        Ws[0][kq * 4 + 1][n] = wr[q].y;
        Ws[0][kq * 4 + 2][n] = wr[q].z;
        Ws[0][kq * 4 + 3][n] = wr[q].w;
    }
    __syncthreads();

    const int NT = DM / BKK;  // 64 k-tiles
    for (int kt = 0; kt < NT; kt++) {
        const int cur = kt & 1;
        if (kt + 1 < NT) {
            const int kb = (kt + 1) * BKK;
#pragma unroll
            for (int q = 0; q < 2; q++) {
                int idx = tid + q * 256;
                int row = idx >> 2, kq = idx & 3;
                xr[q] = *(const float4*)(x + (size_t)(m0 + row) * DM + kb + kq * 4);
            }
#pragma unroll
            for (int q = 0; q < 3; q++) {
                int idx = tid + q * 256;
                int n = idx >> 2, kq = idx & 3;
                const float* src = (n < 64) ? Wd : ((n < 128) ? Wb : Wc);
                wr[q] = *(const float4*)(src + (size_t)(n & 63) * DM + kb + kq * 4);
            }
        }
        // ---- compute on buffer cur ----
#pragma unroll
        for (int k = 0; k < BKK; k++) {
            float4 a0 = *(const float4*)&Xs[cur][k][ty * 8];
            float4 a1 = *(const float4*)&Xs[cur][k][ty * 8 + 4];
            longlong2 w0 = *(const longlong2*)&Ws[cur][k][tx * 12];
            longlong2 w1 = *(const longlong2*)&Ws[cur][k][tx * 12 + 4];
            longlong2 w2 = *(const longlong2*)&Ws[cur][k][tx * 12 + 8];
            unsigned long long bp[6] = {
                (unsigned long long)w0.x, (unsigned long long)w0.y,
                (unsigned long long)w1.x, (unsigned long long)w1.y,
                (unsigned long long)w2.x, (unsigned long long)w2.y};
            float av[8] = {a0.x, a0.y, a0.z, a0.w, a1.x, a1.y, a1.z, a1.w};
#pragma unroll
            for (int r = 0; r < 8; r++) {
                unsigned long long a2 = pk2(av[r], av[r]);
#pragma unroll
                for (int p = 0; p < 6; p++) fma2(acc[r][p], a2, bp[p]);
            }
        }
        if (kt + 1 < NT) {
            const int nxt = (kt + 1) & 1;
#pragma unroll
            for (int q = 0; q < 2; q++) {
                int idx = tid + q * 256;
                int row = idx >> 2, kq = idx & 3;
                Xs[nxt][kq * 4 + 0][row] = xr[q].x;
                Xs[nxt][kq * 4 + 1][row] = xr[q].y;
                Xs[nxt][kq * 4 + 2][row] = xr[q].z;
                Xs[nxt][kq * 4 + 3][row] = xr[q].w;
            }
#pragma unroll
            for (int q = 0; q < 3; q++) {
                int idx = tid + q * 256;
                int n = idx >> 2, kq = idx & 3;
                Ws[nxt][kq * 4 + 0][n] = wr[q].x;
                Ws[nxt][kq * 4 + 1][n] = wr[q].y;
                Ws[nxt][kq * 4 + 2][n] = wr[q].z;
                Ws[nxt][kq * 4 + 3][n] = wr[q].w;
            }
            __syncthreads();
        }
    }

    // ---- epilogue: route into delta / u / C scratch ----
#pragma unroll
    for (int r = 0; r < 8; r++) {
        const int m = m0 + ty * 8 + r;
#pragma unroll
        for (int p = 0; p < 6; p++) {
            float2 v = upk2(acc[r][p]);
            int n0 = tx * 12 + 2 * p;
#pragma unroll
            for (int h = 0; h < 2; h++) {
                int n = n0 + h;
                float val = (h == 0) ? v.x : v.y;
                if (n < 64) {
                    g_delta[(size_t)m * NS + n] = softplus_f(val + bd[n]);
                } else if (n < 128) {
                    int j = n - 64;
                    g_u[(size_t)m * NS + j] = (val + bb[j]) * x[(size_t)m * DM + j];
                } else {
                    int j = n - 128;
                    g_c[(size_t)m * NS + j] = val + bc[j];
                }
            }
        }
    }
}

// ------------------------------- recurrence ---------------------------------
// grid 128 blocks x 128 threads; block -> (batch = bx>>4, 4 rows i).
// warp w handles row i = (bx&15)*4 + w; lane l owns j in {2l, 2l+1}.
// 16-step chunks staged through smem (double buffered, one sync per chunk);
// per-step dot partials buffered in smem, transposed reduce every 16 steps.
#define CH 16
#define NCHUNK (SQ / CH)   // 128

__global__ void __launch_bounds__(128, 1)
recur_kernel(const float* __restrict__ A_log, float* __restrict__ out) {
    __shared__ float sd[2][CH][NS];
    __shared__ float su[2][CH][NS];
    __shared__ float sc[2][CH][NS];
    __shared__ float red[4][CH][33];

    const int tid  = threadIdx.x;
    const int w    = tid >> 5;
    const int l    = tid & 31;
    const int b    = blockIdx.x >> 4;
    const int i    = ((blockIdx.x & 15) << 2) + w;
    const size_t rowbase = (size_t)b * SQ * NS;   // element offset of (b, t=0)

    const float a0 = A_log[i * NS + 2 * l];
    const float a1 = A_log[i * NS + 2 * l + 1];

    const float4* pd = (const float4*)(g_delta + rowbase);
    const float4* pu = (const float4*)(g_u + rowbase);
    const float4* pc = (const float4*)(g_c + rowbase);
    // one chunk = CH*NS = 1024 floats = 256 float4; 128 threads -> 2 each/array
    float4 rd[2], ru[2], rc[2];

#pragma unroll
    for (int q = 0; q < 2; q++) {
        int idx = tid + q * 128;
        rd[q] = pd[idx];
        ru[q] = pu[idx];
        rc[q] = pc[idx];
    }
#pragma unroll
    for (int q = 0; q < 2; q++) {
        int idx = tid + q * 128;
        ((float4*)&sd[0][0][0])[idx] = rd[q];
        ((float4*)&su[0][0][0])[idx] = ru[q];
        ((float4*)&sc[0][0][0])[idx] = rc[q];
    }
    __syncthreads();

    float h0 = 0.0f, h1 = 0.0f;

    for (int c = 0; c < NCHUNK; c++) {
        const int cur = c & 1;
        if (c + 1 < NCHUNK) {
            const int off = (c + 1) * (CH * NS / 4);
#pragma unroll
            for (int q = 0; q < 2; q++) {
                int idx = tid + q * 128;
                rd[q] = pd[off + idx];
                ru[q] = pu[off + idx];
                rc[q] = pc[off + idx];
            }
        }
        // ---- 16 recurrence steps ----
#pragma unroll
        for (int s = 0; s < CH; s++) {
            float d = sd[cur][s][i];
            float2 uv = *(const float2*)&su[cur][s][2 * l];
            float2 cv = *(const float2*)&sc[cur][s][2 * l];
            h0 = __expf(a0 * d) * h0 + uv.x;
            h1 = __expf(a1 * d) * h1 + uv.y;
            red[w][s][l] = cv.x * h0 + cv.y * h1;
        }
        __syncwarp();
        // ---- transposed reduce: lane l -> (step = l&15, half = l>>4) ----
        {
            const int sl = l & 15;
            const int hh = l >> 4;
            float accv = 0.0f;
#pragma unroll
            for (int cc = 0; cc < 16; cc++) accv += red[w][sl][hh * 16 + cc];
            accv += __shfl_xor_sync(0xffffffffu, accv, 16);
            if (l < 16) {
                out[(rowbase + (size_t)(c * CH + l) * NS) + i] = accv;
            }
        }
        __syncwarp();
        if (c + 1 < NCHUNK) {
            const int nxt = (c + 1) & 1;
#pragma unroll
            for (int q = 0; q < 2; q++) {
                int idx = tid + q * 128;
                ((float4*)&sd[nxt][0][0])[idx] = rd[q];
                ((float4*)&su[nxt][0][0])[idx] = ru[q];
                ((float4*)&sc[nxt][0][0])[idx] = rc[q];
            }
            __syncthreads();
        }
    }
}

// --------------------------------- launch -----------------------------------
extern "C" void kernel_launch(void* const* d_in, const int* in_sizes, int n_in,
                              void* d_out, int out_size) {
    const float* x  = (const float*)d_in[0];
    const float* Wd = (const float*)d_in[7];
    const float* bd = (const float*)d_in[8];
    const float* Wb = (const float*)d_in[9];
    const float* bb = (const float*)d_in[10];
    const float* Wc = (const float*)d_in[11];
    const float* bc = (const float*)d_in[12];
    const float* A  = (const float*)d_in[13];
    float* out = (float*)d_out;

    proj_kernel<<<ROWS / BM, 256>>>(x, Wd, bd, Wb, bb, Wc, bc);
    recur_kernel<<<128, 128>>>(A, out);
}

// round 2
// speedup vs baseline: 1.2493x; 1.2493x over previous
#include <cuda_runtime.h>
#include <math.h>

// ---------------------------------------------------------------------------
// SelectiveStateSpace: B=8, S=2048, D_MODEL=1024, N=64
//   proj_kernel : P = X @ [Wd|Wb|Wc]^T ; delta=softplus, u=Bt*x[:, :64], C
//   scan1       : per-chunk local scan (zero init) -> h_end, sum(delta)
//   scan2       : sequential chunk-combine -> h_start per chunk
//   scan3       : per-chunk scan with h_start init -> y
// ---------------------------------------------------------------------------

#define BQ   8
#define SQ   2048
#define DM   1024
#define NS   64
#define ROWS (BQ * SQ)        // 16384
#define RQ   (BQ * NS)        // 512 recurrence rows
#define GQ   8                // chunks per row
#define LQ   (SQ / GQ)        // 256 steps per chunk
#define TS   16               // steps per smem tile
#define NTIL (LQ / TS)        // 16 tiles per chunk

#define LOG2E 1.4426950408889634f

// scratch (device globals; no allocation allowed)
__device__ float g_delta[ROWS * NS];
__device__ float g_u[ROWS * NS];
__device__ float g_c[ROWS * NS];
__device__ float g_hend[RQ * GQ * NS];
__device__ float g_hstart[RQ * GQ * NS];
__device__ float g_dsum[RQ * GQ];

// ------------------------------- f32x2 helpers ------------------------------
__device__ __forceinline__ unsigned long long pk2(float lo, float hi) {
    unsigned long long r;
    asm("mov.b64 %0, {%1, %2};" : "=l"(r) : "f"(lo), "f"(hi));
    return r;
}
__device__ __forceinline__ void fma2(unsigned long long& d, unsigned long long a,
                                     unsigned long long b) {
    asm("fma.rn.f32x2 %0, %1, %2, %0;" : "+l"(d) : "l"(a), "l"(b));
}
__device__ __forceinline__ float2 upk2(unsigned long long v) {
    float2 f;
    asm("mov.b64 {%0, %1}, %2;" : "=f"(f.x), "=f"(f.y) : "l"(v));
    return f;
}

__device__ __forceinline__ float softplus_f(float v) {
    return (v > 20.0f) ? v : log1pf(expf(v));
}

// ------------------------------ projection GEMM -----------------------------
// BM=128 rows, BN=192 cols (delta|Bp|Cp), BK=16, 256 threads, thread tile 8x12.
#define BM 128
#define BN 192
#define BKK 16

__global__ void __launch_bounds__(256, 1)
proj_kernel(const float* __restrict__ x,
            const float* __restrict__ Wd, const float* __restrict__ bd,
            const float* __restrict__ Wb, const float* __restrict__ bb,
            const float* __restrict__ Wc, const float* __restrict__ bc) {
    __shared__ float Xs[2][BKK][BM];
    __shared__ float Ws[2][BKK][BN];

    const int tid = threadIdx.x;
    const int tx  = tid & 15;    // n-tile
    const int ty  = tid >> 4;    // m-tile
    const int m0  = blockIdx.x * BM;

    unsigned long long acc[8][6];
#pragma unroll
    for (int r = 0; r < 8; r++)
#pragma unroll
        for (int p = 0; p < 6; p++) acc[r][p] = 0ull;

    float4 xr[2], wr[3];

#pragma unroll
    for (int q = 0; q < 2; q++) {
        int idx = tid + q * 256;
        int row = idx >> 2, kq = idx & 3;
        xr[q] = *(const float4*)(x + (size_t)(m0 + row) * DM + kq * 4);
    }
#pragma unroll
    for (int q = 0; q < 3; q++) {
        int idx = tid + q * 256;
        int n = idx >> 2, kq = idx & 3;
        const float* src = (n < 64) ? Wd : ((n < 128) ? Wb : Wc);
        wr[q] = *(const float4*)(src + (size_t)(n & 63) * DM + kq * 4);
    }
#pragma unroll
    for (int q = 0; q < 2; q++) {
        int idx = tid + q * 256;
        int row = idx >> 2, kq = idx & 3;
        Xs[0][kq * 4 + 0][row] = xr[q].x;
        Xs[0][kq * 4 + 1][row] = xr[q].y;
        Xs[0][kq * 4 + 2][row] = xr[q].z;
        Xs[0][kq * 4 + 3][row] = xr[q].w;
    }
#pragma unroll
    for (int q = 0; q < 3; q++) {
        int idx = tid + q * 256;
        int n = idx >> 2, kq = idx & 3;
        Ws[0][kq * 4 + 0][n] = wr[q].x;
        Ws[0][kq * 4 + 1][n] = wr[q].y;
        Ws[0][kq * 4 + 2][n] = wr[q].z;
        Ws[0][kq * 4 + 3][n] = wr[q].w;
    }
    __syncthreads();

    const int NT = DM / BKK;  // 64 k-tiles
    for (int kt = 0; kt < NT; kt++) {
        const int cur = kt & 1;
        if (kt + 1 < NT) {
            const int kb = (kt + 1) * BKK;
#pragma unroll
            for (int q = 0; q < 2; q++) {
                int idx = tid + q * 256;
                int row = idx >> 2, kq = idx & 3;
                xr[q] = *(const float4*)(x + (size_t)(m0 + row) * DM + kb + kq * 4);
            }
#pragma unroll
            for (int q = 0; q < 3; q++) {
                int idx = tid + q * 256;
                int n = idx >> 2, kq = idx & 3;
                const float* src = (n < 64) ? Wd : ((n < 128) ? Wb : Wc);
                wr[q] = *(const float4*)(src + (size_t)(n & 63) * DM + kb + kq * 4);
            }
        }
#pragma unroll
        for (int k = 0; k < BKK; k++) {
            float4 a0 = *(const float4*)&Xs[cur][k][ty * 8];
            float4 a1 = *(const float4*)&Xs[cur][k][ty * 8 + 4];
            longlong2 w0 = *(const longlong2*)&Ws[cur][k][tx * 12];
            longlong2 w1 = *(const longlong2*)&Ws[cur][k][tx * 12 + 4];
            longlong2 w2 = *(const longlong2*)&Ws[cur][k][tx * 12 + 8];
            unsigned long long bp[6] = {
                (unsigned long long)w0.x, (unsigned long long)w0.y,
                (unsigned long long)w1.x, (unsigned long long)w1.y,
                (unsigned long long)w2.x, (unsigned long long)w2.y};
            float av[8] = {a0.x, a0.y, a0.z, a0.w, a1.x, a1.y, a1.z, a1.w};
#pragma unroll
            for (int r = 0; r < 8; r++) {
                unsigned long long a2 = pk2(av[r], av[r]);
#pragma unroll
                for (int p = 0; p < 6; p++) fma2(acc[r][p], a2, bp[p]);
            }
        }
        if (kt + 1 < NT) {
            const int nxt = (kt + 1) & 1;
#pragma unroll
            for (int q = 0; q < 2; q++) {
                int idx = tid + q * 256;
                int row = idx >> 2, kq = idx & 3;
                Xs[nxt][kq * 4 + 0][row] = xr[q].x;
                Xs[nxt][kq * 4 + 1][row] = xr[q].y;
                Xs[nxt][kq * 4 + 2][row] = xr[q].z;
                Xs[nxt][kq * 4 + 3][row] = xr[q].w;
            }
#pragma unroll
            for (int q = 0; q < 3; q++) {
                int idx = tid + q * 256;
                int n = idx >> 2, kq = idx & 3;
                Ws[nxt][kq * 4 + 0][n] = wr[q].x;
                Ws[nxt][kq * 4 + 1][n] = wr[q].y;
                Ws[nxt][kq * 4 + 2][n] = wr[q].z;
                Ws[nxt][kq * 4 + 3][n] = wr[q].w;
            }
            __syncthreads();
        }
    }

#pragma unroll
    for (int r = 0; r < 8; r++) {
        const int m = m0 + ty * 8 + r;
#pragma unroll
        for (int p = 0; p < 6; p++) {
            float2 v = upk2(acc[r][p]);
            int n0 = tx * 12 + 2 * p;
#pragma unroll
            for (int h = 0; h < 2; h++) {
                int n = n0 + h;
                float val = (h == 0) ? v.x : v.y;
                if (n < 64) {
                    g_delta[(size_t)m * NS + n] = softplus_f(val + bd[n]);
                } else if (n < 128) {
                    int j = n - 64;
                    g_u[(size_t)m * NS + j] = (val + bb[j]) * x[(size_t)m * DM + j];
                } else {
                    int j = n - 128;
                    g_c[(size_t)m * NS + j] = val + bc[j];
                }
            }
        }
    }
}

// ------------------------------- scan pass 1 --------------------------------
// grid 512 blocks (b[8] x chunk[8] x igrp[8]), 256 threads = 8 warps.
// warp w handles row i = igrp*8 + w, lanes own j in {2l, 2l+1}.
// Local chunk scan with h=0: produces h_end and sum(delta).
__global__ void __launch_bounds__(256, 1)
scan1_kernel(const float* __restrict__ A_log) {
    __shared__ float sdt[2][8][TS];     // transposed: [i_local][step]
    __shared__ float sut[2][TS][NS];

    const int tid = threadIdx.x;
    const int w   = tid >> 5;
    const int l   = tid & 31;
    const int bx  = blockIdx.x;
    const int b     = bx >> 6;
    const int chunk = (bx >> 3) & 7;
    const int ig    = bx & 7;
    const int i     = ig * 8 + w;
    const int row   = b * NS + i;
    const int t0    = chunk * LQ;

    const float a0 = A_log[i * NS + 2 * l] * LOG2E;
    const float a1 = A_log[i * NS + 2 * l + 1] * LOG2E;

    const float* ubase = g_u + ((size_t)(b * SQ + t0)) * NS;
    const float* dbase = g_delta + ((size_t)(b * SQ + t0)) * NS + ig * 8;

    const int us = tid >> 4, uj = (tid & 15) << 2;  // u staging: 1 float4/thread
    const int ds = tid >> 3, di = tid & 7;          // delta staging: tid<128

    float4 ru = *(const float4*)(ubase + (size_t)us * NS + uj);
    float rdel = (tid < 128) ? dbase[(size_t)ds * NS + di] : 0.0f;
    *(float4*)&sut[0][us][uj] = ru;
    if (tid < 128) sdt[0][di][ds] = rdel;
    __syncthreads();

    float h0 = 0.0f, h1 = 0.0f, dsum = 0.0f;

    for (int tile = 0; tile < NTIL; tile++) {
        const int cur = tile & 1;
        if (tile + 1 < NTIL) {
            const int toff = (tile + 1) * TS;
            ru = *(const float4*)(ubase + (size_t)(toff + us) * NS + uj);
            if (tid < 128) rdel = dbase[(size_t)(toff + ds) * NS + di];
        }
        float dv[TS];
        *(float4*)&dv[0]  = *(const float4*)&sdt[cur][w][0];
        *(float4*)&dv[4]  = *(const float4*)&sdt[cur][w][4];
        *(float4*)&dv[8]  = *(const float4*)&sdt[cur][w][8];
        *(float4*)&dv[12] = *(const float4*)&sdt[cur][w][12];
#pragma unroll
        for (int s = 0; s < TS; s++) {
            float d = dv[s];
            dsum += d;
            float2 uv = *(const float2*)&sut[cur][s][2 * l];
            h0 = exp2f(a0 * d) * h0 + uv.x;
            h1 = exp2f(a1 * d) * h1 + uv.y;
        }
        if (tile + 1 < NTIL) {
            const int nxt = cur ^ 1;
            *(float4*)&sut[nxt][us][uj] = ru;
            if (tid < 128) sdt[nxt][di][ds] = rdel;
            __syncthreads();
        }
    }

    *(float2*)&g_hend[((size_t)row * GQ + chunk) * NS + 2 * l] = make_float2(h0, h1);
    if (l == 0) g_dsum[row * GQ + chunk] = dsum;
}

// ------------------------------- scan pass 2 --------------------------------
// grid 128 x 128: warp per row; sequential combine across GQ chunks.
__global__ void __launch_bounds__(128, 1)
scan2_kernel(const float* __restrict__ A_log) {
    const int tid = threadIdx.x;
    const int w   = tid >> 5;
    const int l   = tid & 31;
    const int row = blockIdx.x * 4 + w;
    const int i   = row & (NS - 1);

    const float a0 = A_log[i * NS + 2 * l] * LOG2E;
    const float a1 = A_log[i * NS + 2 * l + 1] * LOG2E;

    float h0 = 0.0f, h1 = 0.0f;
#pragma unroll
    for (int k = 0; k < GQ; k++) {
        const size_t base = ((size_t)row * GQ + k) * NS + 2 * l;
        *(float2*)&g_hstart[base] = make_float2(h0, h1);
        const float D = g_dsum[row * GQ + k];
        float2 he = *(const float2*)&g_hend[base];
        h0 = exp2f(a0 * D) * h0 + he.x;
        h1 = exp2f(a1 * D) * h1 + he.y;
    }
}

// ------------------------------- scan pass 3 --------------------------------
// Same decomposition as pass 1, but h initialized from g_hstart and y emitted.
__global__ void __launch_bounds__(256, 1)
scan3_kernel(const float* __restrict__ A_log, float* __restrict__ out) {
    __shared__ float sdt[2][8][TS];
    __shared__ float sut[2][TS][NS];
    __shared__ float sct[2][TS][NS];
    __shared__ float red[8][TS][33];

    const int tid = threadIdx.x;
    const int w   = tid >> 5;
    const int l   = tid & 31;
    const int bx  = blockIdx.x;
    const int b     = bx >> 6;
    const int chunk = (bx >> 3) & 7;
    const int ig    = bx & 7;
    const int i     = ig * 8 + w;
    const int row   = b * NS + i;
    const int t0    = chunk * LQ;

    const float a0 = A_log[i * NS + 2 * l] * LOG2E;
    const float a1 = A_log[i * NS + 2 * l + 1] * LOG2E;

    float2 hs = *(const float2*)&g_hstart[((size_t)row * GQ + chunk) * NS + 2 * l];
    float h0 = hs.x, h1 = hs.y;

    const float* ubase = g_u + ((size_t)(b * SQ + t0)) * NS;
    const float* cbase = g_c + ((size_t)(b * SQ + t0)) * NS;
    const float* dbase = g_delta + ((size_t)(b * SQ + t0)) * NS + ig * 8;

    const int us = tid >> 4, uj = (tid & 15) << 2;
    const int ds = tid >> 3, di = tid & 7;

    float4 ru = *(const float4*)(ubase + (size_t)us * NS + uj);
    float4 rc = *(const float4*)(cbase + (size_t)us * NS + uj);
    float rdel = (tid < 128) ? dbase[(size_t)ds * NS + di] : 0.0f;
    *(float4*)&sut[0][us][uj] = ru;
    *(float4*)&sct[0][us][uj] = rc;
    if (tid < 128) sdt[0][di][ds] = rdel;
    __syncthreads();

    for (int tile = 0; tile < NTIL; tile++) {
        const int cur = tile & 1;
        if (tile + 1 < NTIL) {
            const int toff = (tile + 1) * TS;
            ru = *(const float4*)(ubase + (size_t)(toff + us) * NS + uj);
            rc = *(const float4*)(cbase + (size_t)(toff + us) * NS + uj);
            if (tid < 128) rdel = dbase[(size_t)(toff + ds) * NS + di];
        }
        float dv[TS];
        *(float4*)&dv[0]  = *(const float4*)&sdt[cur][w][0];
        *(float4*)&dv[4]  = *(const float4*)&sdt[cur][w][4];
        *(float4*)&dv[8]  = *(const float4*)&sdt[cur][w][8];
        *(float4*)&dv[12] = *(const float4*)&sdt[cur][w][12];
#pragma unroll
        for (int s = 0; s < TS; s++) {
            float d = dv[s];
            float2 uv = *(const float2*)&sut[cur][s][2 * l];
            float2 cv = *(const float2*)&sct[cur][s][2 * l];
            h0 = exp2f(a0 * d) * h0 + uv.x;
            h1 = exp2f(a1 * d) * h1 + uv.y;
            red[w][s][l] = cv.x * h0 + cv.y * h1;
        }
        __syncwarp();
        {
            const int sl = l & 15;
            const int hh = l >> 4;
            float accv = 0.0f;
#pragma unroll
            for (int cc = 0; cc < 16; cc++) accv += red[w][sl][hh * 16 + cc];
            accv += __shfl_xor_sync(0xffffffffu, accv, 16);
            if (l < 16) {
                const int t = t0 + tile * TS + sl;
                out[((size_t)(b * SQ + t)) * NS + i] = accv;
            }
        }
        __syncwarp();
        if (tile + 1 < NTIL) {
            const int nxt = cur ^ 1;
            *(float4*)&sut[nxt][us][uj] = ru;
            *(float4*)&sct[nxt][us][uj] = rc;
            if (tid < 128) sdt[nxt][di][ds] = rdel;
            __syncthreads();
        }
    }
}

// --------------------------------- launch -----------------------------------
extern "C" void kernel_launch(void* const* d_in, const int* in_sizes, int n_in,
                              void* d_out, int out_size) {
    const float* x  = (const float*)d_in[0];
    const float* Wd = (const float*)d_in[7];
    const float* bd = (const float*)d_in[8];
    const float* Wb = (const float*)d_in[9];
    const float* bb = (const float*)d_in[10];
    const float* Wc = (const float*)d_in[11];
    const float* bc = (const float*)d_in[12];
    const float* A  = (const float*)d_in[13];
    float* out = (float*)d_out;

    proj_kernel<<<ROWS / BM, 256>>>(x, Wd, bd, Wb, bb, Wc, bc);
    scan1_kernel<<<BQ * GQ * 8, 256>>>(A);
    scan2_kernel<<<RQ / 4, 128>>>(A);
    scan3_kernel<<<BQ * GQ * 8, 256>>>(A, out);
}

// round 4
// speedup vs baseline: 1.8969x; 1.5183x over previous
#include <cuda_runtime.h>
#include <cuda_bf16.h>
#include <math.h>
#include <cstdint>

// ---------------------------------------------------------------------------
// SelectiveStateSpace: B=8, S=2048, D_MODEL=1024, N=64
//   wconv    : W[192,1024] fp32 -> bf16 hi/lo split
//   proj_mma : ldmatrix + mma.sync bf16 3-term GEMM  D = X @ Wcat^T
//              (+ softplus / u / C epilogue)
//   scan1/2/3: chunked parallel scan over t
// NOTE: harness PTX target is compute_103 (no 'a') -> tcgen05 unavailable;
//       legacy mma.sync (sm_80+) is the tensor-core path that compiles.
// ---------------------------------------------------------------------------

#define BQ   8
#define SQ   2048
#define DM   1024
#define NS   64
#define ROWS (BQ * SQ)        // 16384
#define RQ   (BQ * NS)        // 512
#define GQ   8
#define LQ   (SQ / GQ)        // 256
#define TS   16
#define NTIL (LQ / TS)

#define MT   128              // CTA M tile
#define NTOT 192              // CTA N (delta|Bp|Cp)
#define KC   32               // K chunk
#define NKC  (DM / KC)        // 32

#define LOG2E 1.4426950408889634f

// smem geometry (bytes): rows padded to 80B (5 x 16B chunks) for ldmatrix
#define ROWB   80
#define A_TERM (MT * ROWB)            // 10240
#define B_TERM (NTOT * ROWB)          // 15360
#define A_OFF  0
#define B_OFF  (2 * A_TERM)           // 20480 (A hi, A lo)
#define STG_SZ (2 * A_TERM + 2 * B_TERM)  // 51200
#define SMEM_MMA (2 * STG_SZ)         // 102400

// scratch (device globals; no allocation allowed)
__device__ float g_delta[ROWS * NS];
__device__ float g_u[ROWS * NS];
__device__ float g_c[ROWS * NS];
__device__ float g_hend[RQ * GQ * NS];
__device__ float g_hstart[RQ * GQ * NS];
__device__ float g_dsum[RQ * GQ];
__device__ uint4 g_Whi4[NTOT * DM / 8];   // [192][1024] bf16 hi, 8 bf16/uint4
__device__ uint4 g_Wlo4[NTOT * DM / 8];   // bf16 lo

// ------------------------------ helpers -------------------------------------
__device__ __forceinline__ uint32_t smem_u32(const void* p) {
    uint32_t a;
    asm("{ .reg .u64 t; cvta.to.shared.u64 t, %1; cvt.u32.u64 %0, t; }"
        : "=r"(a) : "l"(p));
    return a;
}
__device__ __forceinline__ float softplus_f(float v) {
    return (v > 20.0f) ? v : log1pf(expf(v));
}
__device__ __forceinline__ uint32_t hipack(float a, float b) {
    __nv_bfloat162 h;
    h.x = __float2bfloat16(a);
    h.y = __float2bfloat16(b);
    return *(uint32_t*)&h;
}
__device__ __forceinline__ uint32_t lopack(float a, float b) {
    __nv_bfloat16 ha = __float2bfloat16(a), hb = __float2bfloat16(b);
    __nv_bfloat162 h;
    h.x = __float2bfloat16(a - __bfloat162float(ha));
    h.y = __float2bfloat16(b - __bfloat162float(hb));
    return *(uint32_t*)&h;
}

__device__ __forceinline__ void ldsm4(uint32_t* r, uint32_t addr) {
    asm volatile("ldmatrix.sync.aligned.m8n8.x4.shared.b16 {%0,%1,%2,%3}, [%4];"
                 : "=r"(r[0]), "=r"(r[1]), "=r"(r[2]), "=r"(r[3]) : "r"(addr));
}
__device__ __forceinline__ void mma16816(float* c, const uint32_t* a, const uint32_t* b) {
    asm volatile(
        "mma.sync.aligned.m16n8k16.row.col.f32.bf16.bf16.f32 "
        "{%0,%1,%2,%3}, {%4,%5,%6,%7}, {%8,%9}, {%0,%1,%2,%3};"
        : "+f"(c[0]), "+f"(c[1]), "+f"(c[2]), "+f"(c[3])
        : "r"(a[0]), "r"(a[1]), "r"(a[2]), "r"(a[3]), "r"(b[0]), "r"(b[1]));
}

// ------------------------------ W conversion --------------------------------
__global__ void __launch_bounds__(256, 1)
wconv_kernel(const float* __restrict__ Wd, const float* __restrict__ Wb,
             const float* __restrict__ Wc) {
    int gi = blockIdx.x * 256 + threadIdx.x;       // uint4 index, 0..24575
    int row = gi >> 7;                             // 0..191
    int k8  = (gi & 127) * 8;
    const float* src = (row < 64) ? (Wd + (size_t)row * DM)
                    : (row < 128) ? (Wb + (size_t)(row - 64) * DM)
                                  : (Wc + (size_t)(row - 128) * DM);
    float f[8];
    *(float4*)&f[0] = *(const float4*)(src + k8);
    *(float4*)&f[4] = *(const float4*)(src + k8 + 4);
    uint4 hi, lo;
    hi.x = hipack(f[0], f[1]); hi.y = hipack(f[2], f[3]);
    hi.z = hipack(f[4], f[5]); hi.w = hipack(f[6], f[7]);
    lo.x = lopack(f[0], f[1]); lo.y = lopack(f[2], f[3]);
    lo.z = lopack(f[4], f[5]); lo.w = lopack(f[6], f[7]);
    g_Whi4[gi] = hi;
    g_Wlo4[gi] = lo;
}

// ------------------------------ proj (mma.sync) -----------------------------
__global__ void __launch_bounds__(256, 1)
proj_mma_kernel(const float* __restrict__ x,
                const float* __restrict__ bd, const float* __restrict__ bb,
                const float* __restrict__ bc) {
    extern __shared__ char smem[];
    const uint32_t sb = smem_u32(smem);
    const int tid    = threadIdx.x;
    const int lane   = tid & 31;
    const int warp   = tid >> 5;
    const int warp_m = warp >> 2;      // 0..1
    const int warp_n = warp & 3;       // 0..3
    const int m0     = blockIdx.x * MT;

    float acc[4][6][4];
#pragma unroll
    for (int fm = 0; fm < 4; fm++)
#pragma unroll
        for (int fn = 0; fn < 6; fn++)
#pragma unroll
            for (int e = 0; e < 4; e++) acc[fm][fn][e] = 0.0f;

    // gmem staging regs
    float4 xr[4];
    uint4  wh[3], wl[3];
    const int xrow = tid >> 1;
    const int xco  = (tid & 1) * 16;

#define LDCHUNK(c)                                                              \
    do {                                                                        \
        const float* xp = x + (size_t)(m0 + xrow) * DM + (c) * KC + xco;        \
        xr[0] = *(const float4*)(xp + 0);                                       \
        xr[1] = *(const float4*)(xp + 4);                                       \
        xr[2] = *(const float4*)(xp + 8);                                       \
        xr[3] = *(const float4*)(xp + 12);                                      \
        _Pragma("unroll")                                                       \
        for (int q = 0; q < 3; q++) {                                           \
            int idx = tid + q * 256;                                            \
            int wrow = idx >> 2, wch = idx & 3;                                 \
            int u4 = wrow * 128 + (c) * 4 + wch;                                \
            wh[q] = g_Whi4[u4];                                                 \
            wl[q] = g_Wlo4[u4];                                                 \
        }                                                                       \
    } while (0)

#define STCHUNK(buf)                                                            \
    do {                                                                        \
        char* bs = smem + (buf) * STG_SZ;                                       \
        uint4 h0 = make_uint4(hipack(xr[0].x, xr[0].y), hipack(xr[0].z, xr[0].w),\
                              hipack(xr[1].x, xr[1].y), hipack(xr[1].z, xr[1].w));\
        uint4 h1 = make_uint4(hipack(xr[2].x, xr[2].y), hipack(xr[2].z, xr[2].w),\
                              hipack(xr[3].x, xr[3].y), hipack(xr[3].z, xr[3].w));\
        uint4 l0 = make_uint4(lopack(xr[0].x, xr[0].y), lopack(xr[0].z, xr[0].w),\
                              lopack(xr[1].x, xr[1].y), lopack(xr[1].z, xr[1].w));\
        uint4 l1 = make_uint4(lopack(xr[2].x, xr[2].y), lopack(xr[2].z, xr[2].w),\
                              lopack(xr[3].x, xr[3].y), lopack(xr[3].z, xr[3].w));\
        int ach = (tid & 1) * 2;                                                \
        *(uint4*)(bs + A_OFF + xrow * ROWB + ach * 16)        = h0;             \
        *(uint4*)(bs + A_OFF + xrow * ROWB + (ach + 1) * 16)  = h1;             \
        *(uint4*)(bs + A_OFF + A_TERM + xrow * ROWB + ach * 16)       = l0;     \
        *(uint4*)(bs + A_OFF + A_TERM + xrow * ROWB + (ach + 1) * 16) = l1;     \
        _Pragma("unroll")                                                       \
        for (int q = 0; q < 3; q++) {                                           \
            int idx = tid + q * 256;                                            \
            int wrow = idx >> 2, wch = idx & 3;                                 \
            *(uint4*)(bs + B_OFF + wrow * ROWB + wch * 16) = wh[q];             \
            *(uint4*)(bs + B_OFF + B_TERM + wrow * ROWB + wch * 16) = wl[q];    \
        }                                                                       \
    } while (0)

    LDCHUNK(0);
    STCHUNK(0);
    __syncthreads();
    LDCHUNK(1);

    for (int c = 0; c < NKC; c++) {
        const uint32_t bs = sb + (uint32_t)(c & 1) * STG_SZ;
        // ---- compute chunk c ----
#pragma unroll
        for (int ks = 0; ks < 2; ks++) {
            // lane-static address components
            const int arow_l = (lane & 15);
            const int achk   = ks * 2 + (lane >> 4);
            const int brow_l = (lane & 7) + ((lane >> 4) << 3);
            const int bchk   = ks * 2 + ((lane >> 3) & 1);
#pragma unroll
            for (int term = 0; term < 3; term++) {
                const uint32_t aoff = bs + A_OFF + ((term == 2) ? A_TERM : 0);
                const uint32_t boff = bs + B_OFF + ((term == 1) ? B_TERM : 0);
                uint32_t bfr[6][2];
#pragma unroll
                for (int bn = 0; bn < 3; bn++) {
                    uint32_t r[4];
                    int brow = warp_n * 48 + bn * 16 + brow_l;
                    ldsm4(r, boff + brow * ROWB + bchk * 16);
                    bfr[2 * bn][0] = r[0]; bfr[2 * bn][1] = r[1];
                    bfr[2 * bn + 1][0] = r[2]; bfr[2 * bn + 1][1] = r[3];
                }
#pragma unroll
                for (int fm = 0; fm < 4; fm++) {
                    uint32_t a[4];
                    int arow = warp_m * 64 + fm * 16 + arow_l;
                    ldsm4(a, aoff + arow * ROWB + achk * 16);
#pragma unroll
                    for (int fn = 0; fn < 6; fn++)
                        mma16816(acc[fm][fn], a, bfr[fn]);
                }
            }
        }
        // ---- stage chunk c+1, prefetch c+2 ----
        if (c + 1 < NKC) {
            STCHUNK((c + 1) & 1);
            __syncthreads();
            if (c + 2 < NKC) LDCHUNK(c + 2);
        }
    }

    // ---- epilogue: fragments -> g_delta / g_u / g_c ----
    const int g = lane >> 2;
    const int t = lane & 3;
#pragma unroll
    for (int fn = 0; fn < 6; fn++) {
        const int nblk = warp_n * 48 + fn * 8;
        const int n    = nblk + 2 * t;
#pragma unroll
        for (int fm = 0; fm < 4; fm++) {
#pragma unroll
            for (int half = 0; half < 2; half++) {
                const int m = m0 + warp_m * 64 + fm * 16 + g + half * 8;
                float v0 = acc[fm][fn][2 * half + 0];
                float v1 = acc[fm][fn][2 * half + 1];
                if (nblk < 64) {
                    v0 = softplus_f(v0 + bd[n]);
                    v1 = softplus_f(v1 + bd[n + 1]);
                    *(float2*)&g_delta[(size_t)m * NS + n] = make_float2(v0, v1);
                } else if (nblk < 128) {
                    const int j = n - 64;
                    float2 xv = *(const float2*)&x[(size_t)m * DM + j];
                    v0 = (v0 + bb[j]) * xv.x;
                    v1 = (v1 + bb[j + 1]) * xv.y;
                    *(float2*)&g_u[(size_t)m * NS + j] = make_float2(v0, v1);
                } else {
                    const int j = n - 128;
                    v0 += bc[j];
                    v1 += bc[j + 1];
                    *(float2*)&g_c[(size_t)m * NS + j] = make_float2(v0, v1);
                }
            }
        }
    }
}

// ------------------------------- scan pass 1 --------------------------------
__global__ void __launch_bounds__(256, 1)
scan1_kernel(const float* __restrict__ A_log) {
    __shared__ float sdt[2][8][TS];
    __shared__ float sut[2][TS][NS];

    const int tid = threadIdx.x;
    const int w   = tid >> 5;
    const int l   = tid & 31;
    const int bx  = blockIdx.x;
    const int b     = bx >> 6;
    const int chunk = (bx >> 3) & 7;
    const int ig    = bx & 7;
    const int i     = ig * 8 + w;
    const int row   = b * NS + i;
    const int t0    = chunk * LQ;

    const float a0 = A_log[i * NS + 2 * l] * LOG2E;
    const float a1 = A_log[i * NS + 2 * l + 1] * LOG2E;

    const float* ubase = g_u + ((size_t)(b * SQ + t0)) * NS;
    const float* dbase = g_delta + ((size_t)(b * SQ + t0)) * NS + ig * 8;

    const int us = tid >> 4, uj = (tid & 15) << 2;
    const int ds = tid >> 3, di = tid & 7;

    float4 ru = *(const float4*)(ubase + (size_t)us * NS + uj);
    float rdel = (tid < 128) ? dbase[(size_t)ds * NS + di] : 0.0f;
    *(float4*)&sut[0][us][uj] = ru;
    if (tid < 128) sdt[0][di][ds] = rdel;
    __syncthreads();

    float h0 = 0.0f, h1 = 0.0f, dsum = 0.0f;

    for (int tile = 0; tile < NTIL; tile++) {
        const int cur = tile & 1;
        if (tile + 1 < NTIL) {
            const int toff = (tile + 1) * TS;
            ru = *(const float4*)(ubase + (size_t)(toff + us) * NS + uj);
            if (tid < 128) rdel = dbase[(size_t)(toff + ds) * NS + di];
        }
        float dv[TS];
        *(float4*)&dv[0]  = *(const float4*)&sdt[cur][w][0];
        *(float4*)&dv[4]  = *(const float4*)&sdt[cur][w][4];
        *(float4*)&dv[8]  = *(const float4*)&sdt[cur][w][8];
        *(float4*)&dv[12] = *(const float4*)&sdt[cur][w][12];
#pragma unroll
        for (int s = 0; s < TS; s++) {
            float d = dv[s];
            dsum += d;
            float2 uv = *(const float2*)&sut[cur][s][2 * l];
            h0 = exp2f(a0 * d) * h0 + uv.x;
            h1 = exp2f(a1 * d) * h1 + uv.y;
        }
        if (tile + 1 < NTIL) {
            const int nxt = cur ^ 1;
            *(float4*)&sut[nxt][us][uj] = ru;
            if (tid < 128) sdt[nxt][di][ds] = rdel;
            __syncthreads();
        }
    }

    *(float2*)&g_hend[((size_t)row * GQ + chunk) * NS + 2 * l] = make_float2(h0, h1);
    if (l == 0) g_dsum[row * GQ + chunk] = dsum;
}

// ------------------------------- scan pass 2 --------------------------------
__global__ void __launch_bounds__(128, 1)
scan2_kernel(const float* __restrict__ A_log) {
    const int tid = threadIdx.x;
    const int w   = tid >> 5;
    const int l   = tid & 31;
    const int row = blockIdx.x * 4 + w;
    const int i   = row & (NS - 1);

    const float a0 = A_log[i * NS + 2 * l] * LOG2E;
    const float a1 = A_log[i * NS + 2 * l + 1] * LOG2E;

    float h0 = 0.0f, h1 = 0.0f;
#pragma unroll
    for (int k = 0; k < GQ; k++) {
        const size_t base = ((size_t)row * GQ + k) * NS + 2 * l;
        *(float2*)&g_hstart[base] = make_float2(h0, h1);
        const float D = g_dsum[row * GQ + k];
        float2 he = *(const float2*)&g_hend[base];
        h0 = exp2f(a0 * D) * h0 + he.x;
        h1 = exp2f(a1 * D) * h1 + he.y;
    }
}

// ------------------------------- scan pass 3 --------------------------------
__global__ void __launch_bounds__(256, 1)
scan3_kernel(const float* __restrict__ A_log, float* __restrict__ out) {
    __shared__ float sdt[2][8][TS];
    __shared__ float sut[2][TS][NS];
    __shared__ float sct[2][TS][NS];
    __shared__ float red[8][TS][33];

    const int tid = threadIdx.x;
    const int w   = tid >> 5;
    const int l   = tid & 31;
    const int bx  = blockIdx.x;
    const int b     = bx >> 6;
    const int chunk = (bx >> 3) & 7;
    const int ig    = bx & 7;
    const int i     = ig * 8 + w;
    const int row   = b * NS + i;
    const int t0    = chunk * LQ;

    const float a0 = A_log[i * NS + 2 * l] * LOG2E;
    const float a1 = A_log[i * NS + 2 * l + 1] * LOG2E;

    float2 hs = *(const float2*)&g_hstart[((size_t)row * GQ + chunk) * NS + 2 * l];
    float h0 = hs.x, h1 = hs.y;

    const float* ubase = g_u + ((size_t)(b * SQ + t0)) * NS;
    const float* cbase = g_c + ((size_t)(b * SQ + t0)) * NS;
    const float* dbase = g_delta + ((size_t)(b * SQ + t0)) * NS + ig * 8;

    const int us = tid >> 4, uj = (tid & 15) << 2;
    const int ds = tid >> 3, di = tid & 7;

    float4 ru = *(const float4*)(ubase + (size_t)us * NS + uj);
    float4 rc = *(const float4*)(cbase + (size_t)us * NS + uj);
    float rdel = (tid < 128) ? dbase[(size_t)ds * NS + di] : 0.0f;
    *(float4*)&sut[0][us][uj] = ru;
    *(float4*)&sct[0][us][uj] = rc;
    if (tid < 128) sdt[0][di][ds] = rdel;
    __syncthreads();

    for (int tile = 0; tile < NTIL; tile++) {
        const int cur = tile & 1;
        if (tile + 1 < NTIL) {
            const int toff = (tile + 1) * TS;
            ru = *(const float4*)(ubase + (size_t)(toff + us) * NS + uj);
            rc = *(const float4*)(cbase + (size_t)(toff + us) * NS + uj);
            if (tid < 128) rdel = dbase[(size_t)(toff + ds) * NS + di];
        }
        float dv[TS];
        *(float4*)&dv[0]  = *(const float4*)&sdt[cur][w][0];
        *(float4*)&dv[4]  = *(const float4*)&sdt[cur][w][4];
        *(float4*)&dv[8]  = *(const float4*)&sdt[cur][w][8];
        *(float4*)&dv[12] = *(const float4*)&sdt[cur][w][12];
#pragma unroll
        for (int s = 0; s < TS; s++) {
            float d = dv[s];
            float2 uv = *(const float2*)&sut[cur][s][2 * l];
            float2 cv = *(const float2*)&sct[cur][s][2 * l];
            h0 = exp2f(a0 * d) * h0 + uv.x;
            h1 = exp2f(a1 * d) * h1 + uv.y;
            red[w][s][l] = cv.x * h0 + cv.y * h1;
        }
        __syncwarp();
        {
            const int sl = l & 15;
            const int hh = l >> 4;
            float accv = 0.0f;
#pragma unroll
            for (int cc = 0; cc < 16; cc++) accv += red[w][sl][hh * 16 + cc];
            accv += __shfl_xor_sync(0xffffffffu, accv, 16);
            if (l < 16) {
                const int t = t0 + tile * TS + sl;
                out[((size_t)(b * SQ + t)) * NS + i] = accv;
            }
        }
        __syncwarp();
        if (tile + 1 < NTIL) {
            const int nxt = cur ^ 1;
            *(float4*)&sut[nxt][us][uj] = ru;
            *(float4*)&sct[nxt][us][uj] = rc;
            if (tid < 128) sdt[nxt][di][ds] = rdel;
            __syncthreads();
        }
    }
}

// --------------------------------- launch -----------------------------------
extern "C" void kernel_launch(void* const* d_in, const int* in_sizes, int n_in,
                              void* d_out, int out_size) {
    const float* x  = (const float*)d_in[0];
    const float* Wd = (const float*)d_in[7];
    const float* bd = (const float*)d_in[8];
    const float* Wb = (const float*)d_in[9];
    const float* bb = (const float*)d_in[10];
    const float* Wc = (const float*)d_in[11];
    const float* bc = (const float*)d_in[12];
    const float* A  = (const float*)d_in[13];
    float* out = (float*)d_out;

    cudaFuncSetAttribute(proj_mma_kernel,
                         cudaFuncAttributeMaxDynamicSharedMemorySize, SMEM_MMA);

    wconv_kernel<<<NTOT * DM / 8 / 256, 256>>>(Wd, Wb, Wc);
    proj_mma_kernel<<<ROWS / MT, 256, SMEM_MMA>>>(x, bd, bb, bc);
    scan1_kernel<<<BQ * GQ * 8, 256>>>(A);
    scan2_kernel<<<RQ / 4, 128>>>(A);
    scan3_kernel<<<BQ * GQ * 8, 256>>>(A, out);
}

// round 5
// speedup vs baseline: 2.0514x; 1.0815x over previous
#include <cuda_runtime.h>
#include <cuda_bf16.h>
#include <math.h>
#include <cstdint>

// ---------------------------------------------------------------------------
// SelectiveStateSpace: B=8, S=2048, D_MODEL=1024, N=64
//   wconv    : W[192,1024] fp32 -> bf16 hi/lo split
//   proj_mma : ldmatrix + mma.sync bf16 3-term GEMM  D = X @ Wcat^T
//   scan1    : per-chunk local scan (zero init) -> h_end, sum(delta)
//   scan3    : lookback over (h_end,dsum) -> h_start, then scan, emit y
// GQ=32 chunks/row for occupancy; scan2 eliminated via in-kernel lookback.
// ---------------------------------------------------------------------------

#define BQ   8
#define SQ   2048
#define DM   1024
#define NS   64
#define ROWS (BQ * SQ)        // 16384
#define RQ   (BQ * NS)        // 512
#define GQ   32               // chunks per row
#define LQ   (SQ / GQ)        // 64 steps per chunk
#define TS   16
#define NTIL (LQ / TS)        // 4

#define MT   128
#define NTOT 192
#define KC   32
#define NKC  (DM / KC)        // 32

#define LOG2E 1.4426950408889634f

// smem geometry (bytes): rows padded to 80B (5 x 16B chunks) for ldmatrix
#define ROWB   80
#define A_TERM (MT * ROWB)
#define B_TERM (NTOT * ROWB)
#define A_OFF  0
#define B_OFF  (2 * A_TERM)
#define STG_SZ (2 * A_TERM + 2 * B_TERM)
#define SMEM_MMA (2 * STG_SZ)

// scratch (device globals; no allocation allowed)
__device__ float g_delta[ROWS * NS];
__device__ float g_u[ROWS * NS];
__device__ float g_c[ROWS * NS];
__device__ float g_hend[RQ * GQ * NS];
__device__ float g_dsum[RQ * GQ];
__device__ uint4 g_Whi4[NTOT * DM / 8];
__device__ uint4 g_Wlo4[NTOT * DM / 8];

// ------------------------------ helpers -------------------------------------
__device__ __forceinline__ uint32_t smem_u32(const void* p) {
    uint32_t a;
    asm("{ .reg .u64 t; cvta.to.shared.u64 t, %1; cvt.u32.u64 %0, t; }"
        : "=r"(a) : "l"(p));
    return a;
}
__device__ __forceinline__ float softplus_f(float v) {
    return (v > 20.0f) ? v : log1pf(expf(v));
}
__device__ __forceinline__ uint32_t hipack(float a, float b) {
    __nv_bfloat162 h;
    h.x = __float2bfloat16(a);
    h.y = __float2bfloat16(b);
    return *(uint32_t*)&h;
}
__device__ __forceinline__ uint32_t lopack(float a, float b) {
    __nv_bfloat16 ha = __float2bfloat16(a), hb = __float2bfloat16(b);
    __nv_bfloat162 h;
    h.x = __float2bfloat16(a - __bfloat162float(ha));
    h.y = __float2bfloat16(b - __bfloat162float(hb));
    return *(uint32_t*)&h;
}
__device__ __forceinline__ void ldsm4(uint32_t* r, uint32_t addr) {
    asm volatile("ldmatrix.sync.aligned.m8n8.x4.shared.b16 {%0,%1,%2,%3}, [%4];"
                 : "=r"(r[0]), "=r"(r[1]), "=r"(r[2]), "=r"(r[3]) : "r"(addr));
}
__device__ __forceinline__ void mma16816(float* c, const uint32_t* a, const uint32_t* b) {
    asm volatile(
        "mma.sync.aligned.m16n8k16.row.col.f32.bf16.bf16.f32 "
        "{%0,%1,%2,%3}, {%4,%5,%6,%7}, {%8,%9}, {%0,%1,%2,%3};"
        : "+f"(c[0]), "+f"(c[1]), "+f"(c[2]), "+f"(c[3])
        : "r"(a[0]), "r"(a[1]), "r"(a[2]), "r"(a[3]), "r"(b[0]), "r"(b[1]));
}

// ------------------------------ W conversion --------------------------------
__global__ void __launch_bounds__(256, 1)
wconv_kernel(const float* __restrict__ Wd, const float* __restrict__ Wb,
             const float* __restrict__ Wc) {
    int gi = blockIdx.x * 256 + threadIdx.x;
    int row = gi >> 7;
    int k8  = (gi & 127) * 8;
    const float* src = (row < 64) ? (Wd + (size_t)row * DM)
                    : (row < 128) ? (Wb + (size_t)(row - 64) * DM)
                                  : (Wc + (size_t)(row - 128) * DM);
    float f[8];
    *(float4*)&f[0] = *(const float4*)(src + k8);
    *(float4*)&f[4] = *(const float4*)(src + k8 + 4);
    uint4 hi, lo;
    hi.x = hipack(f[0], f[1]); hi.y = hipack(f[2], f[3]);
    hi.z = hipack(f[4], f[5]); hi.w = hipack(f[6], f[7]);
    lo.x = lopack(f[0], f[1]); lo.y = lopack(f[2], f[3]);
    lo.z = lopack(f[4], f[5]); lo.w = lopack(f[6], f[7]);
    g_Whi4[gi] = hi;
    g_Wlo4[gi] = lo;
}

// ------------------------------ proj (mma.sync) -----------------------------
__global__ void __launch_bounds__(256, 1)
proj_mma_kernel(const float* __restrict__ x,
                const float* __restrict__ bd, const float* __restrict__ bb,
                const float* __restrict__ bc) {
    extern __shared__ char smem[];
    const uint32_t sb = smem_u32(smem);
    const int tid    = threadIdx.x;
    const int lane   = tid & 31;
    const int warp   = tid >> 5;
    const int warp_m = warp >> 2;
    const int warp_n = warp & 3;
    const int m0     = blockIdx.x * MT;

    float acc[4][6][4];
#pragma unroll
    for (int fm = 0; fm < 4; fm++)
#pragma unroll
        for (int fn = 0; fn < 6; fn++)
#pragma unroll
            for (int e = 0; e < 4; e++) acc[fm][fn][e] = 0.0f;

    float4 xr[4];
    uint4  wh[3], wl[3];
    const int xrow = tid >> 1;
    const int xco  = (tid & 1) * 16;

#define LDCHUNK(c)                                                              \
    do {                                                                        \
        const float* xp = x + (size_t)(m0 + xrow) * DM + (c) * KC + xco;        \
        xr[0] = *(const float4*)(xp + 0);                                       \
        xr[1] = *(const float4*)(xp + 4);                                       \
        xr[2] = *(const float4*)(xp + 8);                                       \
        xr[3] = *(const float4*)(xp + 12);                                      \
        _Pragma("unroll")                                                       \
        for (int q = 0; q < 3; q++) {                                           \
            int idx = tid + q * 256;                                            \
            int wrow = idx >> 2, wch = idx & 3;                                 \
            int u4 = wrow * 128 + (c) * 4 + wch;                                \
            wh[q] = g_Whi4[u4];                                                 \
            wl[q] = g_Wlo4[u4];                                                 \
        }                                                                       \
    } while (0)

#define STCHUNK(buf)                                                            \
    do {                                                                        \
        char* bs = smem + (buf) * STG_SZ;                                       \
        uint4 h0 = make_uint4(hipack(xr[0].x, xr[0].y), hipack(xr[0].z, xr[0].w),\
                              hipack(xr[1].x, xr[1].y), hipack(xr[1].z, xr[1].w));\
        uint4 h1 = make_uint4(hipack(xr[2].x, xr[2].y), hipack(xr[2].z, xr[2].w),\
                              hipack(xr[3].x, xr[3].y), hipack(xr[3].z, xr[3].w));\
        uint4 l0 = make_uint4(lopack(xr[0].x, xr[0].y), lopack(xr[0].z, xr[0].w),\
                              lopack(xr[1].x, xr[1].y), lopack(xr[1].z, xr[1].w));\
        uint4 l1 = make_uint4(lopack(xr[2].x, xr[2].y), lopack(xr[2].z, xr[2].w),\
                              lopack(xr[3].x, xr[3].y), lopack(xr[3].z, xr[3].w));\
        int ach = (tid & 1) * 2;                                                \
        *(uint4*)(bs + A_OFF + xrow * ROWB + ach * 16)        = h0;             \
        *(uint4*)(bs + A_OFF + xrow * ROWB + (ach + 1) * 16)  = h1;             \
        *(uint4*)(bs + A_OFF + A_TERM + xrow * ROWB + ach * 16)       = l0;     \
        *(uint4*)(bs + A_OFF + A_TERM + xrow * ROWB + (ach + 1) * 16) = l1;     \
        _Pragma("unroll")                                                       \
        for (int q = 0; q < 3; q++) {                                           \
            int idx = tid + q * 256;                                            \
            int wrow = idx >> 2, wch = idx & 3;                                 \
            *(uint4*)(bs + B_OFF + wrow * ROWB + wch * 16) = wh[q];             \
            *(uint4*)(bs + B_OFF + B_TERM + wrow * ROWB + wch * 16) = wl[q];    \
        }                                                                       \
    } while (0)

    LDCHUNK(0);
    STCHUNK(0);
    __syncthreads();
    LDCHUNK(1);

    for (int c = 0; c < NKC; c++) {
        const uint32_t bs = sb + (uint32_t)(c & 1) * STG_SZ;
#pragma unroll
        for (int ks = 0; ks < 2; ks++) {
            const int arow_l = (lane & 15);
            const int achk   = ks * 2 + (lane >> 4);
            const int brow_l = (lane & 7) + ((lane >> 4) << 3);
            const int bchk   = ks * 2 + ((lane >> 3) & 1);
#pragma unroll
            for (int term = 0; term < 3; term++) {
                const uint32_t aoff = bs + A_OFF + ((term == 2) ? A_TERM : 0);
                const uint32_t boff = bs + B_OFF + ((term == 1) ? B_TERM : 0);
                uint32_t bfr[6][2];
#pragma unroll
                for (int bn = 0; bn < 3; bn++) {
                    uint32_t r[4];
                    int brow = warp_n * 48 + bn * 16 + brow_l;
                    ldsm4(r, boff + brow * ROWB + bchk * 16);
                    bfr[2 * bn][0] = r[0]; bfr[2 * bn][1] = r[1];
                    bfr[2 * bn + 1][0] = r[2]; bfr[2 * bn + 1][1] = r[3];
                }
#pragma unroll
                for (int fm = 0; fm < 4; fm++) {
                    uint32_t a[4];
                    int arow = warp_m * 64 + fm * 16 + arow_l;
                    ldsm4(a, aoff + arow * ROWB + achk * 16);
#pragma unroll
                    for (int fn = 0; fn < 6; fn++)
                        mma16816(acc[fm][fn], a, bfr[fn]);
                }
            }
        }
        if (c + 1 < NKC) {
            STCHUNK((c + 1) & 1);
            __syncthreads();
            if (c + 2 < NKC) LDCHUNK(c + 2);
        }
    }

    const int g = lane >> 2;
    const int t = lane & 3;
#pragma unroll
    for (int fn = 0; fn < 6; fn++) {
        const int nblk = warp_n * 48 + fn * 8;
        const int n    = nblk + 2 * t;
#pragma unroll
        for (int fm = 0; fm < 4; fm++) {
#pragma unroll
            for (int half = 0; half < 2; half++) {
                const int m = m0 + warp_m * 64 + fm * 16 + g + half * 8;
                float v0 = acc[fm][fn][2 * half + 0];
                float v1 = acc[fm][fn][2 * half + 1];
                if (nblk < 64) {
                    v0 = softplus_f(v0 + bd[n]);
                    v1 = softplus_f(v1 + bd[n + 1]);
                    *(float2*)&g_delta[(size_t)m * NS + n] = make_float2(v0, v1);
                } else if (nblk < 128) {
                    const int j = n - 64;
                    float2 xv = *(const float2*)&x[(size_t)m * DM + j];
                    v0 = (v0 + bb[j]) * xv.x;
                    v1 = (v1 + bb[j + 1]) * xv.y;
                    *(float2*)&g_u[(size_t)m * NS + j] = make_float2(v0, v1);
                } else {
                    const int j = n - 128;
                    v0 += bc[j];
                    v1 += bc[j + 1];
                    *(float2*)&g_c[(size_t)m * NS + j] = make_float2(v0, v1);
                }
            }
        }
    }
}

// ------------------------------- scan pass 1 --------------------------------
// grid 2048 (b[8] x chunk[32] x igrp[8]), 256 thr = 8 warps.
__global__ void __launch_bounds__(256, 1)
scan1_kernel(const float* __restrict__ A_log) {
    __shared__ float sdt[2][8][TS];
    __shared__ float sut[2][TS][NS];

    const int tid = threadIdx.x;
    const int w   = tid >> 5;
    const int l   = tid & 31;
    const int bx  = blockIdx.x;
    const int b     = bx >> 8;
    const int chunk = (bx >> 3) & 31;
    const int ig    = bx & 7;
    const int i     = ig * 8 + w;
    const int row   = b * NS + i;
    const int t0    = chunk * LQ;

    const float a0 = A_log[i * NS + 2 * l] * LOG2E;
    const float a1 = A_log[i * NS + 2 * l + 1] * LOG2E;

    const float* ubase = g_u + ((size_t)(b * SQ + t0)) * NS;
    const float* dbase = g_delta + ((size_t)(b * SQ + t0)) * NS + ig * 8;

    const int us = tid >> 4, uj = (tid & 15) << 2;
    const int ds = tid >> 3, di = tid & 7;

    float4 ru = *(const float4*)(ubase + (size_t)us * NS + uj);
    float rdel = (tid < 128) ? dbase[(size_t)ds * NS + di] : 0.0f;
    *(float4*)&sut[0][us][uj] = ru;
    if (tid < 128) sdt[0][di][ds] = rdel;
    __syncthreads();

    float h0 = 0.0f, h1 = 0.0f, dsum = 0.0f;

    for (int tile = 0; tile < NTIL; tile++) {
        const int cur = tile & 1;
        if (tile + 1 < NTIL) {
            const int toff = (tile + 1) * TS;
            ru = *(const float4*)(ubase + (size_t)(toff + us) * NS + uj);
            if (tid < 128) rdel = dbase[(size_t)(toff + ds) * NS + di];
        }
        float dv[TS];
        *(float4*)&dv[0]  = *(const float4*)&sdt[cur][w][0];
        *(float4*)&dv[4]  = *(const float4*)&sdt[cur][w][4];
        *(float4*)&dv[8]  = *(const float4*)&sdt[cur][w][8];
        *(float4*)&dv[12] = *(const float4*)&sdt[cur][w][12];
#pragma unroll
        for (int s = 0; s < TS; s++) {
            float d = dv[s];
            dsum += d;
            float2 uv = *(const float2*)&sut[cur][s][2 * l];
            h0 = exp2f(a0 * d) * h0 + uv.x;
            h1 = exp2f(a1 * d) * h1 + uv.y;
        }
        if (tile + 1 < NTIL) {
            const int nxt = cur ^ 1;
            *(float4*)&sut[nxt][us][uj] = ru;
            if (tid < 128) sdt[nxt][di][ds] = rdel;
            __syncthreads();
        }
    }

    *(float2*)&g_hend[((size_t)row * GQ + chunk) * NS + 2 * l] = make_float2(h0, h1);
    if (l == 0) g_dsum[row * GQ + chunk] = dsum;
}

// ------------------------------- scan pass 3 --------------------------------
// Lookback combine (replaces scan2) + local rescan emitting y.
__global__ void __launch_bounds__(256, 1)
scan3_kernel(const float* __restrict__ A_log, float* __restrict__ out) {
    __shared__ float sdt[2][8][TS];
    __shared__ float sut[2][TS][NS];
    __shared__ float sct[2][TS][NS];
    __shared__ float red[8][TS][33];

    const int tid = threadIdx.x;
    const int w   = tid >> 5;
    const int l   = tid & 31;
    const int bx  = blockIdx.x;
    const int b     = bx >> 8;
    const int chunk = (bx >> 3) & 31;
    const int ig    = bx & 7;
    const int i     = ig * 8 + w;
    const int row   = b * NS + i;
    const int t0    = chunk * LQ;

    const float a0 = A_log[i * NS + 2 * l] * LOG2E;
    const float a1 = A_log[i * NS + 2 * l + 1] * LOG2E;

    const float* ubase = g_u + ((size_t)(b * SQ + t0)) * NS;
    const float* cbase = g_c + ((size_t)(b * SQ + t0)) * NS;
    const float* dbase = g_delta + ((size_t)(b * SQ + t0)) * NS + ig * 8;

    const int us = tid >> 4, uj = (tid & 15) << 2;
    const int ds = tid >> 3, di = tid & 7;

    // stage tile 0 first (hides lookback latency behind LDGs)
    float4 ru = *(const float4*)(ubase + (size_t)us * NS + uj);
    float4 rc = *(const float4*)(cbase + (size_t)us * NS + uj);
    float rdel = (tid < 128) ? dbase[(size_t)ds * NS + di] : 0.0f;
    *(float4*)&sut[0][us][uj] = ru;
    *(float4*)&sct[0][us][uj] = rc;
    if (tid < 128) sdt[0][di][ds] = rdel;

    // ---- lookback: h_start = sum_{p<chunk} exp2(a * S_p) * h_end[p] ----
    float h0 = 0.0f, h1 = 0.0f;
    {
        float S = 0.0f;
        const float* dsp = g_dsum + row * GQ;
        const float* hep = g_hend + ((size_t)row * GQ) * NS + 2 * l;
        for (int p = chunk - 1; p >= 0; p--) {
            float2 he = *(const float2*)(hep + (size_t)p * NS);
            float e0 = exp2f(a0 * S), e1 = exp2f(a1 * S);
            h0 += e0 * he.x;
            h1 += e1 * he.y;
            S += dsp[p];
        }
    }
    __syncthreads();

    for (int tile = 0; tile < NTIL; tile++) {
        const int cur = tile & 1;
        if (tile + 1 < NTIL) {
            const int toff = (tile + 1) * TS;
            ru = *(const float4*)(ubase + (size_t)(toff + us) * NS + uj);
            rc = *(const float4*)(cbase + (size_t)(toff + us) * NS + uj);
            if (tid < 128) rdel = dbase[(size_t)(toff + ds) * NS + di];
        }
        float dv[TS];
        *(float4*)&dv[0]  = *(const float4*)&sdt[cur][w][0];
        *(float4*)&dv[4]  = *(const float4*)&sdt[cur][w][4];
        *(float4*)&dv[8]  = *(const float4*)&sdt[cur][w][8];
        *(float4*)&dv[12] = *(const float4*)&sdt[cur][w][12];
#pragma unroll
        for (int s = 0; s < TS; s++) {
            float d = dv[s];
            float2 uv = *(const float2*)&sut[cur][s][2 * l];
            float2 cv = *(const float2*)&sct[cur][s][2 * l];
            h0 = exp2f(a0 * d) * h0 + uv.x;
            h1 = exp2f(a1 * d) * h1 + uv.y;
            red[w][s][l] = cv.x * h0 + cv.y * h1;
        }
        __syncwarp();
        {
            const int sl = l & 15;
            const int hh = l >> 4;
            float accv = 0.0f;
#pragma unroll
            for (int cc = 0; cc < 16; cc++) accv += red[w][sl][hh * 16 + cc];
            accv += __shfl_xor_sync(0xffffffffu, accv, 16);
            if (l < 16) {
                const int t = t0 + tile * TS + sl;
                out[((size_t)(b * SQ + t)) * NS + i] = accv;
            }
        }
        __syncwarp();
        if (tile + 1 < NTIL) {
            const int nxt = cur ^ 1;
            *(float4*)&sut[nxt][us][uj] = ru;
            *(float4*)&sct[nxt][us][uj] = rc;
            if (tid < 128) sdt[nxt][di][ds] = rdel;
            __syncthreads();
        }
    }
}

// --------------------------------- launch -----------------------------------
extern "C" void kernel_launch(void* const* d_in, const int* in_sizes, int n_in,
                              void* d_out, int out_size) {
    const float* x  = (const float*)d_in[0];
    const float* Wd = (const float*)d_in[7];
    const float* bd = (const float*)d_in[8];
    const float* Wb = (const float*)d_in[9];
    const float* bb = (const float*)d_in[10];
    const float* Wc = (const float*)d_in[11];
    const float* bc = (const float*)d_in[12];
    const float* A  = (const float*)d_in[13];
    float* out = (float*)d_out;

    cudaFuncSetAttribute(proj_mma_kernel,
                         cudaFuncAttributeMaxDynamicSharedMemorySize, SMEM_MMA);

    wconv_kernel<<<NTOT * DM / 8 / 256, 256>>>(Wd, Wb, Wc);
    proj_mma_kernel<<<ROWS / MT, 256, SMEM_MMA>>>(x, bd, bb, bc);
    scan1_kernel<<<BQ * GQ * 8, 256>>>(A);
    scan3_kernel<<<BQ * GQ * 8, 256>>>(A, out);
}

// round 6
// speedup vs baseline: 2.1822x; 1.0638x over previous
#include <cuda_runtime.h>
#include <cuda_bf16.h>
#include <math.h>
#include <cstdint>

// ---------------------------------------------------------------------------
// SelectiveStateSpace: B=8, S=2048, D_MODEL=1024, N=64
//   wconv    : W[192,1024] fp32 -> bf16 hi/lo split
//   proj_mma : ldmatrix + mma.sync bf16 3-term GEMM  D = X @ Wcat^T
//   scan1    : per-chunk local scan (zero init) -> h_end, sum(delta)
//   scan3    : lookback -> h_start, rescan, emit y
// Scan layout: warp owns 4 i-rows, lane owns 8 j's (bank-friendly split);
// u/C smem reads broadcast across i-groups; dot via shfl_xor (no red buffer).
// ---------------------------------------------------------------------------

#define BQ   8
#define SQ   2048
#define DM   1024
#define NS   64
#define ROWS (BQ * SQ)        // 16384
#define RQ   (BQ * NS)        // 512
#define GQ   32               // chunks per row
#define LQ   (SQ / GQ)        // 64 steps per chunk
#define TS   16
#define NTIL (LQ / TS)        // 4

#define MT   128
#define NTOT 192
#define KC   32
#define NKC  (DM / KC)        // 32

#define LOG2E 1.4426950408889634f

// proj smem geometry (bytes): rows padded to 80B for ldmatrix
#define ROWB   80
#define A_TERM (MT * ROWB)
#define B_TERM (NTOT * ROWB)
#define A_OFF  0
#define B_OFF  (2 * A_TERM)
#define STG_SZ (2 * A_TERM + 2 * B_TERM)
#define SMEM_MMA (2 * STG_SZ)

// scratch (device globals; no allocation allowed)
__device__ float g_delta[ROWS * NS];
__device__ float g_u[ROWS * NS];
__device__ float g_c[ROWS * NS];
__device__ float g_hend[RQ * GQ * NS];
__device__ float g_dsum[RQ * GQ];
__device__ uint4 g_Whi4[NTOT * DM / 8];
__device__ uint4 g_Wlo4[NTOT * DM / 8];

// ------------------------------ helpers -------------------------------------
__device__ __forceinline__ uint32_t smem_u32(const void* p) {
    uint32_t a;
    asm("{ .reg .u64 t; cvta.to.shared.u64 t, %1; cvt.u32.u64 %0, t; }"
        : "=r"(a) : "l"(p));
    return a;
}
__device__ __forceinline__ float softplus_f(float v) {
    return (v > 20.0f) ? v : log1pf(expf(v));
}
__device__ __forceinline__ uint32_t hipack(float a, float b) {
    __nv_bfloat162 h;
    h.x = __float2bfloat16(a);
    h.y = __float2bfloat16(b);
    return *(uint32_t*)&h;
}
__device__ __forceinline__ uint32_t lopack(float a, float b) {
    __nv_bfloat16 ha = __float2bfloat16(a), hb = __float2bfloat16(b);
    __nv_bfloat162 h;
    h.x = __float2bfloat16(a - __bfloat162float(ha));
    h.y = __float2bfloat16(b - __bfloat162float(hb));
    return *(uint32_t*)&h;
}
__device__ __forceinline__ void ldsm4(uint32_t* r, uint32_t addr) {
    asm volatile("ldmatrix.sync.aligned.m8n8.x4.shared.b16 {%0,%1,%2,%3}, [%4];"
                 : "=r"(r[0]), "=r"(r[1]), "=r"(r[2]), "=r"(r[3]) : "r"(addr));
}
__device__ __forceinline__ void mma16816(float* c, const uint32_t* a, const uint32_t* b) {
    asm volatile(
        "mma.sync.aligned.m16n8k16.row.col.f32.bf16.bf16.f32 "
        "{%0,%1,%2,%3}, {%4,%5,%6,%7}, {%8,%9}, {%0,%1,%2,%3};"
        : "+f"(c[0]), "+f"(c[1]), "+f"(c[2]), "+f"(c[3])
        : "r"(a[0]), "r"(a[1]), "r"(a[2]), "r"(a[3]), "r"(b[0]), "r"(b[1]));
}

// ------------------------------ W conversion --------------------------------
__global__ void __launch_bounds__(256, 1)
wconv_kernel(const float* __restrict__ Wd, const float* __restrict__ Wb,
             const float* __restrict__ Wc) {
    int gi = blockIdx.x * 256 + threadIdx.x;
    int row = gi >> 7;
    int k8  = (gi & 127) * 8;
    const float* src = (row < 64) ? (Wd + (size_t)row * DM)
                    : (row < 128) ? (Wb + (size_t)(row - 64) * DM)
                                  : (Wc + (size_t)(row - 128) * DM);
    float f[8];
    *(float4*)&f[0] = *(const float4*)(src + k8);
    *(float4*)&f[4] = *(const float4*)(src + k8 + 4);
    uint4 hi, lo;
    hi.x = hipack(f[0], f[1]); hi.y = hipack(f[2], f[3]);
    hi.z = hipack(f[4], f[5]); hi.w = hipack(f[6], f[7]);
    lo.x = lopack(f[0], f[1]); lo.y = lopack(f[2], f[3]);
    lo.z = lopack(f[4], f[5]); lo.w = lopack(f[6], f[7]);
    g_Whi4[gi] = hi;
    g_Wlo4[gi] = lo;
}

// ------------------------------ proj (mma.sync) -----------------------------
__global__ void __launch_bounds__(256, 1)
proj_mma_kernel(const float* __restrict__ x,
                const float* __restrict__ bd, const float* __restrict__ bb,
                const float* __restrict__ bc) {
    extern __shared__ char smem[];
    const uint32_t sb = smem_u32(smem);
    const int tid    = threadIdx.x;
    const int lane   = tid & 31;
    const int warp   = tid >> 5;
    const int warp_m = warp >> 2;
    const int warp_n = warp & 3;
    const int m0     = blockIdx.x * MT;

    float acc[4][6][4];
#pragma unroll
    for (int fm = 0; fm < 4; fm++)
#pragma unroll
        for (int fn = 0; fn < 6; fn++)
#pragma unroll
            for (int e = 0; e < 4; e++) acc[fm][fn][e] = 0.0f;

    float4 xr[4];
    uint4  wh[3], wl[3];
    const int xrow = tid >> 1;
    const int xco  = (tid & 1) * 16;

#define LDCHUNK(c)                                                              \
    do {                                                                        \
        const float* xp = x + (size_t)(m0 + xrow) * DM + (c) * KC + xco;        \
        xr[0] = *(const float4*)(xp + 0);                                       \
        xr[1] = *(const float4*)(xp + 4);                                       \
        xr[2] = *(const float4*)(xp + 8);                                       \
        xr[3] = *(const float4*)(xp + 12);                                      \
        _Pragma("unroll")                                                       \
        for (int q = 0; q < 3; q++) {                                           \
            int idx = tid + q * 256;                                            \
            int wrow = idx >> 2, wch = idx & 3;                                 \
            int u4 = wrow * 128 + (c) * 4 + wch;                                \
            wh[q] = g_Whi4[u4];                                                 \
            wl[q] = g_Wlo4[u4];                                                 \
        }                                                                       \
    } while (0)

#define STCHUNK(buf)                                                            \
    do {                                                                        \
        char* bs = smem + (buf) * STG_SZ;                                       \
        uint4 h0 = make_uint4(hipack(xr[0].x, xr[0].y), hipack(xr[0].z, xr[0].w),\
                              hipack(xr[1].x, xr[1].y), hipack(xr[1].z, xr[1].w));\
        uint4 h1 = make_uint4(hipack(xr[2].x, xr[2].y), hipack(xr[2].z, xr[2].w),\
                              hipack(xr[3].x, xr[3].y), hipack(xr[3].z, xr[3].w));\
        uint4 l0 = make_uint4(lopack(xr[0].x, xr[0].y), lopack(xr[0].z, xr[0].w),\
                              lopack(xr[1].x, xr[1].y), lopack(xr[1].z, xr[1].w));\
        uint4 l1 = make_uint4(lopack(xr[2].x, xr[2].y), lopack(xr[2].z, xr[2].w),\
                              lopack(xr[3].x, xr[3].y), lopack(xr[3].z, xr[3].w));\
        int ach = (tid & 1) * 2;                                                \
        *(uint4*)(bs + A_OFF + xrow * ROWB + ach * 16)        = h0;             \
        *(uint4*)(bs + A_OFF + xrow * ROWB + (ach + 1) * 16)  = h1;             \
        *(uint4*)(bs + A_OFF + A_TERM + xrow * ROWB + ach * 16)       = l0;     \
        *(uint4*)(bs + A_OFF + A_TERM + xrow * ROWB + (ach + 1) * 16) = l1;     \
        _Pragma("unroll")                                                       \
        for (int q = 0; q < 3; q++) {                                           \
            int idx = tid + q * 256;                                            \
            int wrow = idx >> 2, wch = idx & 3;                                 \
            *(uint4*)(bs + B_OFF + wrow * ROWB + wch * 16) = wh[q];             \
            *(uint4*)(bs + B_OFF + B_TERM + wrow * ROWB + wch * 16) = wl[q];    \
        }                                                                       \
    } while (0)

    LDCHUNK(0);
    STCHUNK(0);
    __syncthreads();
    LDCHUNK(1);

    for (int c = 0; c < NKC; c++) {
        const uint32_t bs = sb + (uint32_t)(c & 1) * STG_SZ;
#pragma unroll
        for (int ks = 0; ks < 2; ks++) {
            const int arow_l = (lane & 15);
            const int achk   = ks * 2 + (lane >> 4);
            const int brow_l = (lane & 7) + ((lane >> 4) << 3);
            const int bchk   = ks * 2 + ((lane >> 3) & 1);
#pragma unroll
            for (int term = 0; term < 3; term++) {
                const uint32_t aoff = bs + A_OFF + ((term == 2) ? A_TERM : 0);
                const uint32_t boff = bs + B_OFF + ((term == 1) ? B_TERM : 0);
                uint32_t bfr[6][2];
#pragma unroll
                for (int bn = 0; bn < 3; bn++) {
                    uint32_t r[4];
                    int brow = warp_n * 48 + bn * 16 + brow_l;
                    ldsm4(r, boff + brow * ROWB + bchk * 16);
                    bfr[2 * bn][0] = r[0]; bfr[2 * bn][1] = r[1];
                    bfr[2 * bn + 1][0] = r[2]; bfr[2 * bn + 1][1] = r[3];
                }
#pragma unroll
                for (int fm = 0; fm < 4; fm++) {
                    uint32_t a[4];
                    int arow = warp_m * 64 + fm * 16 + arow_l;
                    ldsm4(a, aoff + arow * ROWB + achk * 16);
#pragma unroll
                    for (int fn = 0; fn < 6; fn++)
                        mma16816(acc[fm][fn], a, bfr[fn]);
                }
            }
        }
        if (c + 1 < NKC) {
            STCHUNK((c + 1) & 1);
            __syncthreads();
            if (c + 2 < NKC) LDCHUNK(c + 2);
        }
    }

    const int g = lane >> 2;
    const int t = lane & 3;
#pragma unroll
    for (int fn = 0; fn < 6; fn++) {
        const int nblk = warp_n * 48 + fn * 8;
        const int n    = nblk + 2 * t;
#pragma unroll
        for (int fm = 0; fm < 4; fm++) {
#pragma unroll
            for (int half = 0; half < 2; half++) {
                const int m = m0 + warp_m * 64 + fm * 16 + g + half * 8;
                float v0 = acc[fm][fn][2 * half + 0];
                float v1 = acc[fm][fn][2 * half + 1];
                if (nblk < 64) {
                    v0 = softplus_f(v0 + bd[n]);
                    v1 = softplus_f(v1 + bd[n + 1]);
                    *(float2*)&g_delta[(size_t)m * NS + n] = make_float2(v0, v1);
                } else if (nblk < 128) {
                    const int j = n - 64;
                    float2 xv = *(const float2*)&x[(size_t)m * DM + j];
                    v0 = (v0 + bb[j]) * xv.x;
                    v1 = (v1 + bb[j + 1]) * xv.y;
                    *(float2*)&g_u[(size_t)m * NS + j] = make_float2(v0, v1);
                } else {
                    const int j = n - 128;
                    v0 += bc[j];
                    v1 += bc[j + 1];
                    *(float2*)&g_c[(size_t)m * NS + j] = make_float2(v0, v1);
                }
            }
        }
    }
}

// ------------------------------- scan pass 1 --------------------------------
// grid 512 (b[8] x chunk[32] x half[2]), 256 thr = 8 warps x 4 i-rows.
// lane: isub = l>>3 (row in warp), g = l&7 (j-slice: 4g..4g+3 and 32+4g..+3).
__global__ void __launch_bounds__(256, 1)
scan1_kernel(const float* __restrict__ A_log) {
    __shared__ float su[2][TS][NS];
    __shared__ float sd[2][TS][NS];

    const int tid = threadIdx.x;
    const int w   = tid >> 5;
    const int l   = tid & 31;
    const int isub = l >> 3;
    const int g    = l & 7;
    const int bx  = blockIdx.x;
    const int b     = bx >> 6;
    const int chunk = (bx >> 1) & 31;
    const int half  = bx & 1;
    const int i     = half * 32 + w * 4 + isub;
    const int row   = b * NS + i;
    const int t0    = chunk * LQ;

    float a[8];
    *(float4*)&a[0] = *(const float4*)&A_log[i * NS + 4 * g];
    *(float4*)&a[4] = *(const float4*)&A_log[i * NS + 32 + 4 * g];
#pragma unroll
    for (int k = 0; k < 8; k++) a[k] *= LOG2E;

    const float* ubase = g_u + ((size_t)(b * SQ + t0)) * NS;
    const float* dbase = g_delta + ((size_t)(b * SQ + t0)) * NS;

    const int ss = tid >> 4, sp = (tid & 15) << 2;  // stage: 1 float4/thread/array

    float4 ru = *(const float4*)(ubase + (size_t)ss * NS + sp);
    float4 rd = *(const float4*)(dbase + (size_t)ss * NS + sp);
    *(float4*)&su[0][ss][sp] = ru;
    *(float4*)&sd[0][ss][sp] = rd;
    __syncthreads();

    float h[8];
#pragma unroll
    for (int k = 0; k < 8; k++) h[k] = 0.0f;
    float dsum = 0.0f;

    for (int tile = 0; tile < NTIL; tile++) {
        const int cur = tile & 1;
        if (tile + 1 < NTIL) {
            const int toff = (tile + 1) * TS;
            ru = *(const float4*)(ubase + (size_t)(toff + ss) * NS + sp);
            rd = *(const float4*)(dbase + (size_t)(toff + ss) * NS + sp);
        }
#pragma unroll
        for (int s = 0; s < TS; s++) {
            float d = sd[cur][s][i];
            dsum += d;
            float4 ua = *(const float4*)&su[cur][s][4 * g];
            float4 ub = *(const float4*)&su[cur][s][32 + 4 * g];
            h[0] = exp2f(a[0] * d) * h[0] + ua.x;
            h[1] = exp2f(a[1] * d) * h[1] + ua.y;
            h[2] = exp2f(a[2] * d) * h[2] + ua.z;
            h[3] = exp2f(a[3] * d) * h[3] + ua.w;
            h[4] = exp2f(a[4] * d) * h[4] + ub.x;
            h[5] = exp2f(a[5] * d) * h[5] + ub.y;
            h[6] = exp2f(a[6] * d) * h[6] + ub.z;
            h[7] = exp2f(a[7] * d) * h[7] + ub.w;
        }
        if (tile + 1 < NTIL) {
            const int nxt = cur ^ 1;
            *(float4*)&su[nxt][ss][sp] = ru;
            *(float4*)&sd[nxt][ss][sp] = rd;
            __syncthreads();
        }
    }

    float* he = g_hend + ((size_t)row * GQ + chunk) * NS;
    *(float4*)(he + 4 * g)      = make_float4(h[0], h[1], h[2], h[3]);
    *(float4*)(he + 32 + 4 * g) = make_float4(h[4], h[5], h[6], h[7]);
    if (g == 0) g_dsum[row * GQ + chunk] = dsum;
}

// ------------------------------- scan pass 3 --------------------------------
__global__ void __launch_bounds__(256, 1)
scan3_kernel(const float* __restrict__ A_log, float* __restrict__ out) {
    __shared__ float su[2][TS][NS];
    __shared__ float sc[2][TS][NS];
    __shared__ float sd[2][TS][NS];
    __shared__ float ys[2][TS][32];

    const int tid = threadIdx.x;
    const int w   = tid >> 5;
    const int l   = tid & 31;
    const int isub = l >> 3;
    const int g    = l & 7;
    const int bx  = blockIdx.x;
    const int b     = bx >> 6;
    const int chunk = (bx >> 1) & 31;
    const int half  = bx & 1;
    const int iblk  = w * 4 + isub;          // 0..31
    const int i     = half * 32 + iblk;
    const int row   = b * NS + i;
    const int t0    = chunk * LQ;

    float a[8];
    *(float4*)&a[0] = *(const float4*)&A_log[i * NS + 4 * g];
    *(float4*)&a[4] = *(const float4*)&A_log[i * NS + 32 + 4 * g];
#pragma unroll
    for (int k = 0; k < 8; k++) a[k] *= LOG2E;

    const float* ubase = g_u + ((size_t)(b * SQ + t0)) * NS;
    const float* cbase = g_c + ((size_t)(b * SQ + t0)) * NS;
    const float* dbase = g_delta + ((size_t)(b * SQ + t0)) * NS;

    const int ss = tid >> 4, sp = (tid & 15) << 2;

    // stage tile 0 (hides lookback behind LDGs)
    float4 ru = *(const float4*)(ubase + (size_t)ss * NS + sp);
    float4 rc = *(const float4*)(cbase + (size_t)ss * NS + sp);
    float4 rd = *(const float4*)(dbase + (size_t)ss * NS + sp);
    *(float4*)&su[0][ss][sp] = ru;
    *(float4*)&sc[0][ss][sp] = rc;
    *(float4*)&sd[0][ss][sp] = rd;

    // ---- lookback: h_start = sum_{p<chunk} exp2(a * S_p) * h_end[p] ----
    float h[8];
#pragma unroll
    for (int k = 0; k < 8; k++) h[k] = 0.0f;
    {
        float S = 0.0f;
        const float* dsp = g_dsum + row * GQ;
        const float* hep = g_hend + ((size_t)row * GQ) * NS;
        for (int p = chunk - 1; p >= 0; p--) {
            float4 he0 = *(const float4*)(hep + (size_t)p * NS + 4 * g);
            float4 he1 = *(const float4*)(hep + (size_t)p * NS + 32 + 4 * g);
            h[0] += exp2f(a[0] * S) * he0.x;
            h[1] += exp2f(a[1] * S) * he0.y;
            h[2] += exp2f(a[2] * S) * he0.z;
            h[3] += exp2f(a[3] * S) * he0.w;
            h[4] += exp2f(a[4] * S) * he1.x;
            h[5] += exp2f(a[5] * S) * he1.y;
            h[6] += exp2f(a[6] * S) * he1.z;
            h[7] += exp2f(a[7] * S) * he1.w;
            S += dsp[p];
        }
    }
    __syncthreads();

    for (int tile = 0; tile < NTIL; tile++) {
        const int cur = tile & 1;
        if (tile + 1 < NTIL) {
            const int toff = (tile + 1) * TS;
            ru = *(const float4*)(ubase + (size_t)(toff + ss) * NS + sp);
            rc = *(const float4*)(cbase + (size_t)(toff + ss) * NS + sp);
            rd = *(const float4*)(dbase + (size_t)(toff + ss) * NS + sp);
        }
#pragma unroll
        for (int s = 0; s < TS; s++) {
            float d = sd[cur][s][i];
            float4 ua = *(const float4*)&su[cur][s][4 * g];
            float4 ub = *(const float4*)&su[cur][s][32 + 4 * g];
            float4 ca = *(const float4*)&sc[cur][s][4 * g];
            float4 cb = *(const float4*)&sc[cur][s][32 + 4 * g];
            h[0] = exp2f(a[0] * d) * h[0] + ua.x;
            h[1] = exp2f(a[1] * d) * h[1] + ua.y;
            h[2] = exp2f(a[2] * d) * h[2] + ua.z;
            h[3] = exp2f(a[3] * d) * h[3] + ua.w;
            h[4] = exp2f(a[4] * d) * h[4] + ub.x;
            h[5] = exp2f(a[5] * d) * h[5] + ub.y;
            h[6] = exp2f(a[6] * d) * h[6] + ub.z;
            h[7] = exp2f(a[7] * d) * h[7] + ub.w;
            float p = ca.x * h[0] + ca.y * h[1] + ca.z * h[2] + ca.w * h[3]
                    + cb.x * h[4] + cb.y * h[5] + cb.z * h[6] + cb.w * h[7];
            p += __shfl_xor_sync(0xffffffffu, p, 4);
            p += __shfl_xor_sync(0xffffffffu, p, 2);
            p += __shfl_xor_sync(0xffffffffu, p, 1);
            if (g == 0) ys[cur][s][iblk] = p;
        }
        if (tile + 1 < NTIL) {
            const int nxt = cur ^ 1;
            *(float4*)&su[nxt][ss][sp] = ru;
            *(float4*)&sc[nxt][ss][sp] = rc;
            *(float4*)&sd[nxt][ss][sp] = rd;
        }
        __syncthreads();
        // coalesced y writeout for this tile
        {
            const int yt = tid >> 4;            // 0..15
            const int yi = (tid & 15) << 1;     // 0..30
            float2 yv = *(const float2*)&ys[cur][yt][yi];
            const int t = t0 + tile * TS + yt;
            *(float2*)&out[((size_t)(b * SQ + t)) * NS + half * 32 + yi] = yv;
        }
    }
}

// --------------------------------- launch -----------------------------------
extern "C" void kernel_launch(void* const* d_in, const int* in_sizes, int n_in,
                              void* d_out, int out_size) {
    const float* x  = (const float*)d_in[0];
    const float* Wd = (const float*)d_in[7];
    const float* bd = (const float*)d_in[8];
    const float* Wb = (const float*)d_in[9];
    const float* bb = (const float*)d_in[10];
    const float* Wc = (const float*)d_in[11];
    const float* bc = (const float*)d_in[12];
    const float* A  = (const float*)d_in[13];
    float* out = (float*)d_out;

    cudaFuncSetAttribute(proj_mma_kernel,
                         cudaFuncAttributeMaxDynamicSharedMemorySize, SMEM_MMA);

    wconv_kernel<<<NTOT * DM / 8 / 256, 256>>>(Wd, Wb, Wc);
    proj_mma_kernel<<<ROWS / MT, 256, SMEM_MMA>>>(x, bd, bb, bc);
    scan1_kernel<<<BQ * GQ * 2, 256>>>(A);
    scan3_kernel<<<BQ * GQ * 2, 256>>>(A, out);
}

// round 7
// speedup vs baseline: 2.2249x; 1.0196x over previous
#include <cuda_runtime.h>
#include <cuda_bf16.h>
#include <math.h>
#include <cstdint>

// ---------------------------------------------------------------------------
// SelectiveStateSpace: B=8, S=2048, D_MODEL=1024, N=64
//   wconv    : W[192,1024] fp32 -> bf16 hi/lo split
//   proj_mma : ldmatrix + mma.sync bf16 3-term GEMM  D = X @ Wcat^T
//   scan1    : per-chunk local scan (zero init) -> h_end, sum(delta)
//   scan3    : lookback -> h_start, rescan, emit y
// GQ=16 (128-step chunks): 256 blocks = single wave at 2 blocks/SM.
// ---------------------------------------------------------------------------

#define BQ   8
#define SQ   2048
#define DM   1024
#define NS   64
#define ROWS (BQ * SQ)        // 16384
#define RQ   (BQ * NS)        // 512
#define GQ   16               // chunks per row
#define LQ   (SQ / GQ)        // 128 steps per chunk
#define TS   16
#define NTIL (LQ / TS)        // 8

#define MT   128
#define NTOT 192
#define KC   32
#define NKC  (DM / KC)        // 32

#define LOG2E 1.4426950408889634f

// proj smem geometry (bytes): rows padded to 80B for ldmatrix
#define ROWB   80
#define A_TERM (MT * ROWB)
#define B_TERM (NTOT * ROWB)
#define A_OFF  0
#define B_OFF  (2 * A_TERM)
#define STG_SZ (2 * A_TERM + 2 * B_TERM)
#define SMEM_MMA (2 * STG_SZ)

// scratch (device globals; no allocation allowed)
__device__ float g_delta[ROWS * NS];
__device__ float g_u[ROWS * NS];
__device__ float g_c[ROWS * NS];
__device__ float g_hend[RQ * GQ * NS];
__device__ float g_dsum[RQ * GQ];
__device__ uint4 g_Whi4[NTOT * DM / 8];
__device__ uint4 g_Wlo4[NTOT * DM / 8];

// ------------------------------ helpers -------------------------------------
__device__ __forceinline__ uint32_t smem_u32(const void* p) {
    uint32_t a;
    asm("{ .reg .u64 t; cvta.to.shared.u64 t, %1; cvt.u32.u64 %0, t; }"
        : "=r"(a) : "l"(p));
    return a;
}
__device__ __forceinline__ float softplus_f(float v) {
    return (v > 20.0f) ? v : log1pf(expf(v));
}
__device__ __forceinline__ uint32_t hipack(float a, float b) {
    __nv_bfloat162 h;
    h.x = __float2bfloat16(a);
    h.y = __float2bfloat16(b);
    return *(uint32_t*)&h;
}
__device__ __forceinline__ uint32_t lopack(float a, float b) {
    __nv_bfloat16 ha = __float2bfloat16(a), hb = __float2bfloat16(b);
    __nv_bfloat162 h;
    h.x = __float2bfloat16(a - __bfloat162float(ha));
    h.y = __float2bfloat16(b - __bfloat162float(hb));
    return *(uint32_t*)&h;
}
__device__ __forceinline__ void ldsm4(uint32_t* r, uint32_t addr) {
    asm volatile("ldmatrix.sync.aligned.m8n8.x4.shared.b16 {%0,%1,%2,%3}, [%4];"
                 : "=r"(r[0]), "=r"(r[1]), "=r"(r[2]), "=r"(r[3]) : "r"(addr));
}
__device__ __forceinline__ void mma16816(float* c, const uint32_t* a, const uint32_t* b) {
    asm volatile(
        "mma.sync.aligned.m16n8k16.row.col.f32.bf16.bf16.f32 "
        "{%0,%1,%2,%3}, {%4,%5,%6,%7}, {%8,%9}, {%0,%1,%2,%3};"
        : "+f"(c[0]), "+f"(c[1]), "+f"(c[2]), "+f"(c[3])
        : "r"(a[0]), "r"(a[1]), "r"(a[2]), "r"(a[3]), "r"(b[0]), "r"(b[1]));
}

// ------------------------------ W conversion --------------------------------
__global__ void __launch_bounds__(256, 1)
wconv_kernel(const float* __restrict__ Wd, const float* __restrict__ Wb,
             const float* __restrict__ Wc) {
    int gi = blockIdx.x * 256 + threadIdx.x;
    int row = gi >> 7;
    int k8  = (gi & 127) * 8;
    const float* src = (row < 64) ? (Wd + (size_t)row * DM)
                    : (row < 128) ? (Wb + (size_t)(row - 64) * DM)
                                  : (Wc + (size_t)(row - 128) * DM);
    float f[8];
    *(float4*)&f[0] = *(const float4*)(src + k8);
    *(float4*)&f[4] = *(const float4*)(src + k8 + 4);
    uint4 hi, lo;
    hi.x = hipack(f[0], f[1]); hi.y = hipack(f[2], f[3]);
    hi.z = hipack(f[4], f[5]); hi.w = hipack(f[6], f[7]);
    lo.x = lopack(f[0], f[1]); lo.y = lopack(f[2], f[3]);
    lo.z = lopack(f[4], f[5]); lo.w = lopack(f[6], f[7]);
    g_Whi4[gi] = hi;
    g_Wlo4[gi] = lo;
}

// ------------------------------ proj (mma.sync) -----------------------------
__global__ void __launch_bounds__(256, 1)
proj_mma_kernel(const float* __restrict__ x,
                const float* __restrict__ bd, const float* __restrict__ bb,
                const float* __restrict__ bc) {
    extern __shared__ char smem[];
    const uint32_t sb = smem_u32(smem);
    const int tid    = threadIdx.x;
    const int lane   = tid & 31;
    const int warp   = tid >> 5;
    const int warp_m = warp >> 2;
    const int warp_n = warp & 3;
    const int m0     = blockIdx.x * MT;

    float acc[4][6][4];
#pragma unroll
    for (int fm = 0; fm < 4; fm++)
#pragma unroll
        for (int fn = 0; fn < 6; fn++)
#pragma unroll
            for (int e = 0; e < 4; e++) acc[fm][fn][e] = 0.0f;

    float4 xr[4];
    uint4  wh[3], wl[3];
    const int xrow = tid >> 1;
    const int xco  = (tid & 1) * 16;

#define LDCHUNK(c)                                                              \
    do {                                                                        \
        const float* xp = x + (size_t)(m0 + xrow) * DM + (c) * KC + xco;        \
        xr[0] = *(const float4*)(xp + 0);                                       \
        xr[1] = *(const float4*)(xp + 4);                                       \
        xr[2] = *(const float4*)(xp + 8);                                       \
        xr[3] = *(const float4*)(xp + 12);                                      \
        _Pragma("unroll")                                                       \
        for (int q = 0; q < 3; q++) {                                           \
            int idx = tid + q * 256;                                            \
            int wrow = idx >> 2, wch = idx & 3;                                 \
            int u4 = wrow * 128 + (c) * 4 + wch;                                \
            wh[q] = g_Whi4[u4];                                                 \
            wl[q] = g_Wlo4[u4];                                                 \
        }                                                                       \
    } while (0)

#define STCHUNK(buf)                                                            \
    do {                                                                        \
        char* bs = smem + (buf) * STG_SZ;                                       \
        uint4 h0 = make_uint4(hipack(xr[0].x, xr[0].y), hipack(xr[0].z, xr[0].w),\
                              hipack(xr[1].x, xr[1].y), hipack(xr[1].z, xr[1].w));\
        uint4 h1 = make_uint4(hipack(xr[2].x, xr[2].y), hipack(xr[2].z, xr[2].w),\
                              hipack(xr[3].x, xr[3].y), hipack(xr[3].z, xr[3].w));\
        uint4 l0 = make_uint4(lopack(xr[0].x, xr[0].y), lopack(xr[0].z, xr[0].w),\
                              lopack(xr[1].x, xr[1].y), lopack(xr[1].z, xr[1].w));\
        uint4 l1 = make_uint4(lopack(xr[2].x, xr[2].y), lopack(xr[2].z, xr[2].w),\
                              lopack(xr[3].x, xr[3].y), lopack(xr[3].z, xr[3].w));\
        int ach = (tid & 1) * 2;                                                \
        *(uint4*)(bs + A_OFF + xrow * ROWB + ach * 16)        = h0;             \
        *(uint4*)(bs + A_OFF + xrow * ROWB + (ach + 1) * 16)  = h1;             \
        *(uint4*)(bs + A_OFF + A_TERM + xrow * ROWB + ach * 16)       = l0;     \
        *(uint4*)(bs + A_OFF + A_TERM + xrow * ROWB + (ach + 1) * 16) = l1;     \
        _Pragma("unroll")                                                       \
        for (int q = 0; q < 3; q++) {                                           \
            int idx = tid + q * 256;                                            \
            int wrow = idx >> 2, wch = idx & 3;                                 \
            *(uint4*)(bs + B_OFF + wrow * ROWB + wch * 16) = wh[q];             \
            *(uint4*)(bs + B_OFF + B_TERM + wrow * ROWB + wch * 16) = wl[q];    \
        }                                                                       \
    } while (0)

    LDCHUNK(0);
    STCHUNK(0);
    __syncthreads();
    LDCHUNK(1);

    for (int c = 0; c < NKC; c++) {
        const uint32_t bs = sb + (uint32_t)(c & 1) * STG_SZ;
#pragma unroll
        for (int ks = 0; ks < 2; ks++) {
            const int arow_l = (lane & 15);
            const int achk   = ks * 2 + (lane >> 4);
            const int brow_l = (lane & 7) + ((lane >> 4) << 3);
            const int bchk   = ks * 2 + ((lane >> 3) & 1);
#pragma unroll
            for (int term = 0; term < 3; term++) {
                const uint32_t aoff = bs + A_OFF + ((term == 2) ? A_TERM : 0);
                const uint32_t boff = bs + B_OFF + ((term == 1) ? B_TERM : 0);
                uint32_t bfr[6][2];
#pragma unroll
                for (int bn = 0; bn < 3; bn++) {
                    uint32_t r[4];
                    int brow = warp_n * 48 + bn * 16 + brow_l;
                    ldsm4(r, boff + brow * ROWB + bchk * 16);
                    bfr[2 * bn][0] = r[0]; bfr[2 * bn][1] = r[1];
                    bfr[2 * bn + 1][0] = r[2]; bfr[2 * bn + 1][1] = r[3];
                }
#pragma unroll
                for (int fm = 0; fm < 4; fm++) {
                    uint32_t a[4];
                    int arow = warp_m * 64 + fm * 16 + arow_l;
                    ldsm4(a, aoff + arow * ROWB + achk * 16);
#pragma unroll
                    for (int fn = 0; fn < 6; fn++)
                        mma16816(acc[fm][fn], a, bfr[fn]);
                }
            }
        }
        if (c + 1 < NKC) {
            STCHUNK((c + 1) & 1);
            __syncthreads();
            if (c + 2 < NKC) LDCHUNK(c + 2);
        }
    }

    const int g = lane >> 2;
    const int t = lane & 3;
#pragma unroll
    for (int fn = 0; fn < 6; fn++) {
        const int nblk = warp_n * 48 + fn * 8;
        const int n    = nblk + 2 * t;
#pragma unroll
        for (int fm = 0; fm < 4; fm++) {
#pragma unroll
            for (int half = 0; half < 2; half++) {
                const int m = m0 + warp_m * 64 + fm * 16 + g + half * 8;
                float v0 = acc[fm][fn][2 * half + 0];
                float v1 = acc[fm][fn][2 * half + 1];
                if (nblk < 64) {
                    v0 = softplus_f(v0 + bd[n]);
                    v1 = softplus_f(v1 + bd[n + 1]);
                    *(float2*)&g_delta[(size_t)m * NS + n] = make_float2(v0, v1);
                } else if (nblk < 128) {
                    const int j = n - 64;
                    float2 xv = *(const float2*)&x[(size_t)m * DM + j];
                    v0 = (v0 + bb[j]) * xv.x;
                    v1 = (v1 + bb[j + 1]) * xv.y;
                    *(float2*)&g_u[(size_t)m * NS + j] = make_float2(v0, v1);
                } else {
                    const int j = n - 128;
                    v0 += bc[j];
                    v1 += bc[j + 1];
                    *(float2*)&g_c[(size_t)m * NS + j] = make_float2(v0, v1);
                }
            }
        }
    }
}

// ------------------------------- scan pass 1 --------------------------------
// grid 256 (b[8] x chunk[16] x half[2]), 256 thr = 8 warps x 4 i-rows.
// lane: isub = l>>3 (row in warp), g = l&7 (j-slice: 4g..4g+3 and 32+4g..+3).
__global__ void __launch_bounds__(256, 1)
scan1_kernel(const float* __restrict__ A_log) {
    __shared__ float su[2][TS][NS];
    __shared__ float sd[2][TS][NS];

    const int tid = threadIdx.x;
    const int w   = tid >> 5;
    const int l   = tid & 31;
    const int isub = l >> 3;
    const int g    = l & 7;
    const int bx  = blockIdx.x;
    const int b     = bx >> 5;
    const int chunk = (bx >> 1) & 15;
    const int half  = bx & 1;
    const int i     = half * 32 + w * 4 + isub;
    const int row   = b * NS + i;
    const int t0    = chunk * LQ;

    float a[8];
    *(float4*)&a[0] = *(const float4*)&A_log[i * NS + 4 * g];
    *(float4*)&a[4] = *(const float4*)&A_log[i * NS + 32 + 4 * g];
#pragma unroll
    for (int k = 0; k < 8; k++) a[k] *= LOG2E;

    const float* ubase = g_u + ((size_t)(b * SQ + t0)) * NS;
    const float* dbase = g_delta + ((size_t)(b * SQ + t0)) * NS;

    const int ss = tid >> 4, sp = (tid & 15) << 2;  // stage: 1 float4/thread/array

    float4 ru = *(const float4*)(ubase + (size_t)ss * NS + sp);
    float4 rd = *(const float4*)(dbase + (size_t)ss * NS + sp);
    *(float4*)&su[0][ss][sp] = ru;
    *(float4*)&sd[0][ss][sp] = rd;
    __syncthreads();

    float h[8];
#pragma unroll
    for (int k = 0; k < 8; k++) h[k] = 0.0f;
    float dsum = 0.0f;

    for (int tile = 0; tile < NTIL; tile++) {
        const int cur = tile & 1;
        if (tile + 1 < NTIL) {
            const int toff = (tile + 1) * TS;
            ru = *(const float4*)(ubase + (size_t)(toff + ss) * NS + sp);
            rd = *(const float4*)(dbase + (size_t)(toff + ss) * NS + sp);
        }
#pragma unroll
        for (int s = 0; s < TS; s++) {
            float d = sd[cur][s][i];
            dsum += d;
            float4 ua = *(const float4*)&su[cur][s][4 * g];
            float4 ub = *(const float4*)&su[cur][s][32 + 4 * g];
            h[0] = exp2f(a[0] * d) * h[0] + ua.x;
            h[1] = exp2f(a[1] * d) * h[1] + ua.y;
            h[2] = exp2f(a[2] * d) * h[2] + ua.z;
            h[3] = exp2f(a[3] * d) * h[3] + ua.w;
            h[4] = exp2f(a[4] * d) * h[4] + ub.x;
            h[5] = exp2f(a[5] * d) * h[5] + ub.y;
            h[6] = exp2f(a[6] * d) * h[6] + ub.z;
            h[7] = exp2f(a[7] * d) * h[7] + ub.w;
        }
        if (tile + 1 < NTIL) {
            const int nxt = cur ^ 1;
            *(float4*)&su[nxt][ss][sp] = ru;
            *(float4*)&sd[nxt][ss][sp] = rd;
            __syncthreads();
        }
    }

    float* he = g_hend + ((size_t)row * GQ + chunk) * NS;
    *(float4*)(he + 4 * g)      = make_float4(h[0], h[1], h[2], h[3]);
    *(float4*)(he + 32 + 4 * g) = make_float4(h[4], h[5], h[6], h[7]);
    if (g == 0) g_dsum[row * GQ + chunk] = dsum;
}

// ------------------------------- scan pass 3 --------------------------------
__global__ void __launch_bounds__(256, 1)
scan3_kernel(const float* __restrict__ A_log, float* __restrict__ out) {
    __shared__ float su[2][TS][NS];
    __shared__ float sc[2][TS][NS];
    __shared__ float sd[2][TS][NS];
    __shared__ float ys[2][TS][32];

    const int tid = threadIdx.x;
    const int w   = tid >> 5;
    const int l   = tid & 31;
    const int isub = l >> 3;
    const int g    = l & 7;
    const int bx  = blockIdx.x;
    const int b     = bx >> 5;
    const int chunk = (bx >> 1) & 15;
    const int half  = bx & 1;
    const int iblk  = w * 4 + isub;          // 0..31
    const int i     = half * 32 + iblk;
    const int row   = b * NS + i;
    const int t0    = chunk * LQ;

    float a[8];
    *(float4*)&a[0] = *(const float4*)&A_log[i * NS + 4 * g];
    *(float4*)&a[4] = *(const float4*)&A_log[i * NS + 32 + 4 * g];
#pragma unroll
    for (int k = 0; k < 8; k++) a[k] *= LOG2E;

    const float* ubase = g_u + ((size_t)(b * SQ + t0)) * NS;
    const float* cbase = g_c + ((size_t)(b * SQ + t0)) * NS;
    const float* dbase = g_delta + ((size_t)(b * SQ + t0)) * NS;

    const int ss = tid >> 4, sp = (tid & 15) << 2;

    // stage tile 0 (hides lookback behind LDGs)
    float4 ru = *(const float4*)(ubase + (size_t)ss * NS + sp);
    float4 rc = *(const float4*)(cbase + (size_t)ss * NS + sp);
    float4 rd = *(const float4*)(dbase + (size_t)ss * NS + sp);
    *(float4*)&su[0][ss][sp] = ru;
    *(float4*)&sc[0][ss][sp] = rc;
    *(float4*)&sd[0][ss][sp] = rd;

    // ---- lookback: h_start = sum_{p<chunk} exp2(a * S_p) * h_end[p] ----
    float h[8];
#pragma unroll
    for (int k = 0; k < 8; k++) h[k] = 0.0f;
    {
        float S = 0.0f;
        const float* dsp = g_dsum + row * GQ;
        const float* hep = g_hend + ((size_t)row * GQ) * NS;
        for (int p = chunk - 1; p >= 0; p--) {
            float4 he0 = *(const float4*)(hep + (size_t)p * NS + 4 * g);
            float4 he1 = *(const float4*)(hep + (size_t)p * NS + 32 + 4 * g);
            h[0] += exp2f(a[0] * S) * he0.x;
            h[1] += exp2f(a[1] * S) * he0.y;
            h[2] += exp2f(a[2] * S) * he0.z;
            h[3] += exp2f(a[3] * S) * he0.w;
            h[4] += exp2f(a[4] * S) * he1.x;
            h[5] += exp2f(a[5] * S) * he1.y;
            h[6] += exp2f(a[6] * S) * he1.z;
            h[7] += exp2f(a[7] * S) * he1.w;
            S += dsp[p];
        }
    }
    __syncthreads();

    for (int tile = 0; tile < NTIL; tile++) {
        const int cur = tile & 1;
        if (tile + 1 < NTIL) {
            const int toff = (tile + 1) * TS;
            ru = *(const float4*)(ubase + (size_t)(toff + ss) * NS + sp);
            rc = *(const float4*)(cbase + (size_t)(toff + ss) * NS + sp);
            rd = *(const float4*)(dbase + (size_t)(toff + ss) * NS + sp);
        }
#pragma unroll
        for (int s = 0; s < TS; s++) {
            float d = sd[cur][s][i];
            float4 ua = *(const float4*)&su[cur][s][4 * g];
            float4 ub = *(const float4*)&su[cur][s][32 + 4 * g];
            float4 ca = *(const float4*)&sc[cur][s][4 * g];
            float4 cb = *(const float4*)&sc[cur][s][32 + 4 * g];
            h[0] = exp2f(a[0] * d) * h[0] + ua.x;
            h[1] = exp2f(a[1] * d) * h[1] + ua.y;
            h[2] = exp2f(a[2] * d) * h[2] + ua.z;
            h[3] = exp2f(a[3] * d) * h[3] + ua.w;
            h[4] = exp2f(a[4] * d) * h[4] + ub.x;
            h[5] = exp2f(a[5] * d) * h[5] + ub.y;
            h[6] = exp2f(a[6] * d) * h[6] + ub.z;
            h[7] = exp2f(a[7] * d) * h[7] + ub.w;
            float p = ca.x * h[0] + ca.y * h[1] + ca.z * h[2] + ca.w * h[3]
                    + cb.x * h[4] + cb.y * h[5] + cb.z * h[6] + cb.w * h[7];
            p += __shfl_xor_sync(0xffffffffu, p, 4);
            p += __shfl_xor_sync(0xffffffffu, p, 2);
            p += __shfl_xor_sync(0xffffffffu, p, 1);
            if (g == 0) ys[cur][s][iblk] = p;
        }
        if (tile + 1 < NTIL) {
            const int nxt = cur ^ 1;
            *(float4*)&su[nxt][ss][sp] = ru;
            *(float4*)&sc[nxt][ss][sp] = rc;
            *(float4*)&sd[nxt][ss][sp] = rd;
        }
        __syncthreads();
        // coalesced y writeout for this tile
        {
            const int yt = tid >> 4;            // 0..15
            const int yi = (tid & 15) << 1;     // 0..30
            float2 yv = *(const float2*)&ys[cur][yt][yi];
            const int t = t0 + tile * TS + yt;
            *(float2*)&out[((size_t)(b * SQ + t)) * NS + half * 32 + yi] = yv;
        }
    }
}

// --------------------------------- launch -----------------------------------
extern "C" void kernel_launch(void* const* d_in, const int* in_sizes, int n_in,
                              void* d_out, int out_size) {
    const float* x  = (const float*)d_in[0];
    const float* Wd = (const float*)d_in[7];
    const float* bd = (const float*)d_in[8];
    const float* Wb = (const float*)d_in[9];
    const float* bb = (const float*)d_in[10];
    const float* Wc = (const float*)d_in[11];
    const float* bc = (const float*)d_in[12];
    const float* A  = (const float*)d_in[13];
    float* out = (float*)d_out;

    cudaFuncSetAttribute(proj_mma_kernel,
                         cudaFuncAttributeMaxDynamicSharedMemorySize, SMEM_MMA);

    wconv_kernel<<<NTOT * DM / 8 / 256, 256>>>(Wd, Wb, Wc);
    proj_mma_kernel<<<ROWS / MT, 256, SMEM_MMA>>>(x, bd, bb, bc);
    scan1_kernel<<<BQ * GQ * 2, 256>>>(A);
    scan3_kernel<<<BQ * GQ * 2, 256>>>(A, out);
}

// round 8
// speedup vs baseline: 2.3065x; 1.0367x over previous
#include <cuda_runtime.h>
#include <cuda_bf16.h>
#include <math.h>
#include <cstdint>

// ---------------------------------------------------------------------------
// SelectiveStateSpace: B=8, S=2048, D_MODEL=1024, N=64
//   wconv    : W[192,1024] fp32 -> bf16 hi/lo split
//   proj_mma : ldmatrix + mma.sync bf16 3-term GEMM  D = X @ Wcat^T
//   scan1    : per-chunk local scan (zero init) -> h_end, sum(delta)
//   scan3    : lookback -> h_start, rescan, emit y
// exp2 via raw MUFU (ex2.approx.ftz) -- libdevice exp2f expands to ~15 instrs
// without fast-math and made the scans issue-bound.
// ---------------------------------------------------------------------------

#define BQ   8
#define SQ   2048
#define DM   1024
#define NS   64
#define ROWS (BQ * SQ)        // 16384
#define RQ   (BQ * NS)        // 512
#define GQ   16               // chunks per row
#define LQ   (SQ / GQ)        // 128 steps per chunk
#define TS   16
#define NTIL (LQ / TS)        // 8

#define MT   128
#define NTOT 192
#define KC   32
#define NKC  (DM / KC)        // 32

#define LOG2E 1.4426950408889634f

// proj smem geometry (bytes): rows padded to 80B for ldmatrix
#define ROWB   80
#define A_TERM (MT * ROWB)
#define B_TERM (NTOT * ROWB)
#define A_OFF  0
#define B_OFF  (2 * A_TERM)
#define STG_SZ (2 * A_TERM + 2 * B_TERM)
#define SMEM_MMA (2 * STG_SZ)

// scratch (device globals; no allocation allowed)
__device__ float g_delta[ROWS * NS];
__device__ float g_u[ROWS * NS];
__device__ float g_c[ROWS * NS];
__device__ float g_hend[RQ * GQ * NS];
__device__ float g_dsum[RQ * GQ];
__device__ uint4 g_Whi4[NTOT * DM / 8];
__device__ uint4 g_Wlo4[NTOT * DM / 8];

// ------------------------------ helpers -------------------------------------
__device__ __forceinline__ uint32_t smem_u32(const void* p) {
    uint32_t a;
    asm("{ .reg .u64 t; cvta.to.shared.u64 t, %1; cvt.u32.u64 %0, t; }"
        : "=r"(a) : "l"(p));
    return a;
}
// single-instruction exp2 (MUFU.EX2)
__device__ __forceinline__ float ex2(float x) {
    float r;
    asm("ex2.approx.ftz.f32 %0, %1;" : "=f"(r) : "f"(x));
    return r;
}
__device__ __forceinline__ float softplus_f(float v) {
    return (v > 20.0f) ? v : log1pf(expf(v));
}
__device__ __forceinline__ uint32_t hipack(float a, float b) {
    __nv_bfloat162 h;
    h.x = __float2bfloat16(a);
    h.y = __float2bfloat16(b);
    return *(uint32_t*)&h;
}
__device__ __forceinline__ uint32_t lopack(float a, float b) {
    __nv_bfloat16 ha = __float2bfloat16(a), hb = __float2bfloat16(b);
    __nv_bfloat162 h;
    h.x = __float2bfloat16(a - __bfloat162float(ha));
    h.y = __float2bfloat16(b - __bfloat162float(hb));
    return *(uint32_t*)&h;
}
__device__ __forceinline__ void ldsm4(uint32_t* r, uint32_t addr) {
    asm volatile("ldmatrix.sync.aligned.m8n8.x4.shared.b16 {%0,%1,%2,%3}, [%4];"
                 : "=r"(r[0]), "=r"(r[1]), "=r"(r[2]), "=r"(r[3]) : "r"(addr));
}
__device__ __forceinline__ void mma16816(float* c, const uint32_t* a, const uint32_t* b) {
    asm volatile(
        "mma.sync.aligned.m16n8k16.row.col.f32.bf16.bf16.f32 "
        "{%0,%1,%2,%3}, {%4,%5,%6,%7}, {%8,%9}, {%0,%1,%2,%3};"
        : "+f"(c[0]), "+f"(c[1]), "+f"(c[2]), "+f"(c[3])
        : "r"(a[0]), "r"(a[1]), "r"(a[2]), "r"(a[3]), "r"(b[0]), "r"(b[1]));
}

// ------------------------------ W conversion --------------------------------
__global__ void __launch_bounds__(256, 1)
wconv_kernel(const float* __restrict__ Wd, const float* __restrict__ Wb,
             const float* __restrict__ Wc) {
    int gi = blockIdx.x * 256 + threadIdx.x;
    int row = gi >> 7;
    int k8  = (gi & 127) * 8;
    const float* src = (row < 64) ? (Wd + (size_t)row * DM)
                    : (row < 128) ? (Wb + (size_t)(row - 64) * DM)
                                  : (Wc + (size_t)(row - 128) * DM);
    float f[8];
    *(float4*)&f[0] = *(const float4*)(src + k8);
    *(float4*)&f[4] = *(const float4*)(src + k8 + 4);
    uint4 hi, lo;
    hi.x = hipack(f[0], f[1]); hi.y = hipack(f[2], f[3]);
    hi.z = hipack(f[4], f[5]); hi.w = hipack(f[6], f[7]);
    lo.x = lopack(f[0], f[1]); lo.y = lopack(f[2], f[3]);
    lo.z = lopack(f[4], f[5]); lo.w = lopack(f[6], f[7]);
    g_Whi4[gi] = hi;
    g_Wlo4[gi] = lo;
}

// ------------------------------ proj (mma.sync) -----------------------------
__global__ void __launch_bounds__(256, 1)
proj_mma_kernel(const float* __restrict__ x,
                const float* __restrict__ bd, const float* __restrict__ bb,
                const float* __restrict__ bc) {
    extern __shared__ char smem[];
    const uint32_t sb = smem_u32(smem);
    const int tid    = threadIdx.x;
    const int lane   = tid & 31;
    const int warp   = tid >> 5;
    const int warp_m = warp >> 2;
    const int warp_n = warp & 3;
    const int m0     = blockIdx.x * MT;

    float acc[4][6][4];
#pragma unroll
    for (int fm = 0; fm < 4; fm++)
#pragma unroll
        for (int fn = 0; fn < 6; fn++)
#pragma unroll
            for (int e = 0; e < 4; e++) acc[fm][fn][e] = 0.0f;

    float4 xr[4];
    uint4  wh[3], wl[3];
    const int xrow = tid >> 1;
    const int xco  = (tid & 1) * 16;

#define LDCHUNK(c)                                                              \
    do {                                                                        \
        const float* xp = x + (size_t)(m0 + xrow) * DM + (c) * KC + xco;        \
        xr[0] = *(const float4*)(xp + 0);                                       \
        xr[1] = *(const float4*)(xp + 4);                                       \
        xr[2] = *(const float4*)(xp + 8);                                       \
        xr[3] = *(const float4*)(xp + 12);                                      \
        _Pragma("unroll")                                                       \
        for (int q = 0; q < 3; q++) {                                           \
            int idx = tid + q * 256;                                            \
            int wrow = idx >> 2, wch = idx & 3;                                 \
            int u4 = wrow * 128 + (c) * 4 + wch;                                \
            wh[q] = g_Whi4[u4];                                                 \
            wl[q] = g_Wlo4[u4];                                                 \
        }                                                                       \
    } while (0)

#define STCHUNK(buf)                                                            \
    do {                                                                        \
        char* bs = smem + (buf) * STG_SZ;                                       \
        uint4 h0 = make_uint4(hipack(xr[0].x, xr[0].y), hipack(xr[0].z, xr[0].w),\
                              hipack(xr[1].x, xr[1].y), hipack(xr[1].z, xr[1].w));\
        uint4 h1 = make_uint4(hipack(xr[2].x, xr[2].y), hipack(xr[2].z, xr[2].w),\
                              hipack(xr[3].x, xr[3].y), hipack(xr[3].z, xr[3].w));\
        uint4 l0 = make_uint4(lopack(xr[0].x, xr[0].y), lopack(xr[0].z, xr[0].w),\
                              lopack(xr[1].x, xr[1].y), lopack(xr[1].z, xr[1].w));\
        uint4 l1 = make_uint4(lopack(xr[2].x, xr[2].y), lopack(xr[2].z, xr[2].w),\
                              lopack(xr[3].x, xr[3].y), lopack(xr[3].z, xr[3].w));\
        int ach = (tid & 1) * 2;                                                \
        *(uint4*)(bs + A_OFF + xrow * ROWB + ach * 16)        = h0;             \
        *(uint4*)(bs + A_OFF + xrow * ROWB + (ach + 1) * 16)  = h1;             \
        *(uint4*)(bs + A_OFF + A_TERM + xrow * ROWB + ach * 16)       = l0;     \
        *(uint4*)(bs + A_OFF + A_TERM + xrow * ROWB + (ach + 1) * 16) = l1;     \
        _Pragma("unroll")                                                       \
        for (int q = 0; q < 3; q++) {                                           \
            int idx = tid + q * 256;                                            \
            int wrow = idx >> 2, wch = idx & 3;                                 \
            *(uint4*)(bs + B_OFF + wrow * ROWB + wch * 16) = wh[q];             \
            *(uint4*)(bs + B_OFF + B_TERM + wrow * ROWB + wch * 16) = wl[q];    \
        }                                                                       \
    } while (0)

    LDCHUNK(0);
    STCHUNK(0);
    __syncthreads();
    LDCHUNK(1);

    for (int c = 0; c < NKC; c++) {
        const uint32_t bs = sb + (uint32_t)(c & 1) * STG_SZ;
#pragma unroll
        for (int ks = 0; ks < 2; ks++) {
            const int arow_l = (lane & 15);
            const int achk   = ks * 2 + (lane >> 4);
            const int brow_l = (lane & 7) + ((lane >> 4) << 3);
            const int bchk   = ks * 2 + ((lane >> 3) & 1);
#pragma unroll
            for (int term = 0; term < 3; term++) {
                const uint32_t aoff = bs + A_OFF + ((term == 2) ? A_TERM : 0);
                const uint32_t boff = bs + B_OFF + ((term == 1) ? B_TERM : 0);
                uint32_t bfr[6][2];
#pragma unroll
                for (int bn = 0; bn < 3; bn++) {
                    uint32_t r[4];
                    int brow = warp_n * 48 + bn * 16 + brow_l;
                    ldsm4(r, boff + brow * ROWB + bchk * 16);
                    bfr[2 * bn][0] = r[0]; bfr[2 * bn][1] = r[1];
                    bfr[2 * bn + 1][0] = r[2]; bfr[2 * bn + 1][1] = r[3];
                }
#pragma unroll
                for (int fm = 0; fm < 4; fm++) {
                    uint32_t a[4];
                    int arow = warp_m * 64 + fm * 16 + arow_l;
                    ldsm4(a, aoff + arow * ROWB + achk * 16);
#pragma unroll
                    for (int fn = 0; fn < 6; fn++)
                        mma16816(acc[fm][fn], a, bfr[fn]);
                }
            }
        }
        if (c + 1 < NKC) {
            STCHUNK((c + 1) & 1);
            __syncthreads();
            if (c + 2 < NKC) LDCHUNK(c + 2);
        }
    }

    const int g = lane >> 2;
    const int t = lane & 3;
#pragma unroll
    for (int fn = 0; fn < 6; fn++) {
        const int nblk = warp_n * 48 + fn * 8;
        const int n    = nblk + 2 * t;
#pragma unroll
        for (int fm = 0; fm < 4; fm++) {
#pragma unroll
            for (int half = 0; half < 2; half++) {
                const int m = m0 + warp_m * 64 + fm * 16 + g + half * 8;
                float v0 = acc[fm][fn][2 * half + 0];
                float v1 = acc[fm][fn][2 * half + 1];
                if (nblk < 64) {
                    v0 = softplus_f(v0 + bd[n]);
                    v1 = softplus_f(v1 + bd[n + 1]);
                    *(float2*)&g_delta[(size_t)m * NS + n] = make_float2(v0, v1);
                } else if (nblk < 128) {
                    const int j = n - 64;
                    float2 xv = *(const float2*)&x[(size_t)m * DM + j];
                    v0 = (v0 + bb[j]) * xv.x;
                    v1 = (v1 + bb[j + 1]) * xv.y;
                    *(float2*)&g_u[(size_t)m * NS + j] = make_float2(v0, v1);
                } else {
                    const int j = n - 128;
                    v0 += bc[j];
                    v1 += bc[j + 1];
                    *(float2*)&g_c[(size_t)m * NS + j] = make_float2(v0, v1);
                }
            }
        }
    }
}

// ------------------------------- scan pass 1 --------------------------------
// grid 256 (b[8] x chunk[16] x half[2]), 256 thr = 8 warps x 4 i-rows.
__global__ void __launch_bounds__(256, 1)
scan1_kernel(const float* __restrict__ A_log) {
    __shared__ float su[2][TS][NS];
    __shared__ float sd[2][TS][NS];

    const int tid = threadIdx.x;
    const int w   = tid >> 5;
    const int l   = tid & 31;
    const int isub = l >> 3;
    const int g    = l & 7;
    const int bx  = blockIdx.x;
    const int b     = bx >> 5;
    const int chunk = (bx >> 1) & 15;
    const int half  = bx & 1;
    const int i     = half * 32 + w * 4 + isub;
    const int row   = b * NS + i;
    const int t0    = chunk * LQ;

    float a[8];
    *(float4*)&a[0] = *(const float4*)&A_log[i * NS + 4 * g];
    *(float4*)&a[4] = *(const float4*)&A_log[i * NS + 32 + 4 * g];
#pragma unroll
    for (int k = 0; k < 8; k++) a[k] *= LOG2E;

    const float* ubase = g_u + ((size_t)(b * SQ + t0)) * NS;
    const float* dbase = g_delta + ((size_t)(b * SQ + t0)) * NS;

    const int ss = tid >> 4, sp = (tid & 15) << 2;

    float4 ru = *(const float4*)(ubase + (size_t)ss * NS + sp);
    float4 rd = *(const float4*)(dbase + (size_t)ss * NS + sp);
    *(float4*)&su[0][ss][sp] = ru;
    *(float4*)&sd[0][ss][sp] = rd;
    __syncthreads();

    float h[8];
#pragma unroll
    for (int k = 0; k < 8; k++) h[k] = 0.0f;
    float dsum = 0.0f;

    for (int tile = 0; tile < NTIL; tile++) {
        const int cur = tile & 1;
        if (tile + 1 < NTIL) {
            const int toff = (tile + 1) * TS;
            ru = *(const float4*)(ubase + (size_t)(toff + ss) * NS + sp);
            rd = *(const float4*)(dbase + (size_t)(toff + ss) * NS + sp);
        }
#pragma unroll
        for (int s = 0; s < TS; s++) {
            float d = sd[cur][s][i];
            dsum += d;
            float4 ua = *(const float4*)&su[cur][s][4 * g];
            float4 ub = *(const float4*)&su[cur][s][32 + 4 * g];
            h[0] = ex2(a[0] * d) * h[0] + ua.x;
            h[1] = ex2(a[1] * d) * h[1] + ua.y;
            h[2] = ex2(a[2] * d) * h[2] + ua.z;
            h[3] = ex2(a[3] * d) * h[3] + ua.w;
            h[4] = ex2(a[4] * d) * h[4] + ub.x;
            h[5] = ex2(a[5] * d) * h[5] + ub.y;
            h[6] = ex2(a[6] * d) * h[6] + ub.z;
            h[7] = ex2(a[7] * d) * h[7] + ub.w;
        }
        if (tile + 1 < NTIL) {
            const int nxt = cur ^ 1;
            *(float4*)&su[nxt][ss][sp] = ru;
            *(float4*)&sd[nxt][ss][sp] = rd;
            __syncthreads();
        }
    }

    float* he = g_hend + ((size_t)row * GQ + chunk) * NS;
    *(float4*)(he + 4 * g)      = make_float4(h[0], h[1], h[2], h[3]);
    *(float4*)(he + 32 + 4 * g) = make_float4(h[4], h[5], h[6], h[7]);
    if (g == 0) g_dsum[row * GQ + chunk] = dsum;
}

// ------------------------------- scan pass 3 --------------------------------
__global__ void __launch_bounds__(256, 1)
scan3_kernel(const float* __restrict__ A_log, float* __restrict__ out) {
    __shared__ float su[2][TS][NS];
    __shared__ float sc[2][TS][NS];
    __shared__ float sd[2][TS][NS];
    __shared__ float ys[2][TS][32];

    const int tid = threadIdx.x;
    const int w   = tid >> 5;
    const int l   = tid & 31;
    const int isub = l >> 3;
    const int g    = l & 7;
    const int bx  = blockIdx.x;
    const int b     = bx >> 5;
    const int chunk = (bx >> 1) & 15;
    const int half  = bx & 1;
    const int iblk  = w * 4 + isub;          // 0..31
    const int i     = half * 32 + iblk;
    const int row   = b * NS + i;
    const int t0    = chunk * LQ;

    float a[8];
    *(float4*)&a[0] = *(const float4*)&A_log[i * NS + 4 * g];
    *(float4*)&a[4] = *(const float4*)&A_log[i * NS + 32 + 4 * g];
#pragma unroll
    for (int k = 0; k < 8; k++) a[k] *= LOG2E;

    const float* ubase = g_u + ((size_t)(b * SQ + t0)) * NS;
    const float* cbase = g_c + ((size_t)(b * SQ + t0)) * NS;
    const float* dbase = g_delta + ((size_t)(b * SQ + t0)) * NS;

    const int ss = tid >> 4, sp = (tid & 15) << 2;

    // stage tile 0 (hides lookback behind LDGs)
    float4 ru = *(const float4*)(ubase + (size_t)ss * NS + sp);
    float4 rc = *(const float4*)(cbase + (size_t)ss * NS + sp);
    float4 rd = *(const float4*)(dbase + (size_t)ss * NS + sp);
    *(float4*)&su[0][ss][sp] = ru;
    *(float4*)&sc[0][ss][sp] = rc;
    *(float4*)&sd[0][ss][sp] = rd;

    // ---- lookback: h_start = sum_{p<chunk} exp2(a * S_p) * h_end[p] ----
    float h[8];
#pragma unroll
    for (int k = 0; k < 8; k++) h[k] = 0.0f;
    {
        float S = 0.0f;
        const float* dsp = g_dsum + row * GQ;
        const float* hep = g_hend + ((size_t)row * GQ) * NS;
        for (int p = chunk - 1; p >= 0; p--) {
            float4 he0 = *(const float4*)(hep + (size_t)p * NS + 4 * g);
            float4 he1 = *(const float4*)(hep + (size_t)p * NS + 32 + 4 * g);
            h[0] += ex2(a[0] * S) * he0.x;
            h[1] += ex2(a[1] * S) * he0.y;
            h[2] += ex2(a[2] * S) * he0.z;
            h[3] += ex2(a[3] * S) * he0.w;
            h[4] += ex2(a[4] * S) * he1.x;
            h[5] += ex2(a[5] * S) * he1.y;
            h[6] += ex2(a[6] * S) * he1.z;
            h[7] += ex2(a[7] * S) * he1.w;
            S += dsp[p];
        }
    }
    __syncthreads();

    for (int tile = 0; tile < NTIL; tile++) {
        const int cur = tile & 1;
        if (tile + 1 < NTIL) {
            const int toff = (tile + 1) * TS;
            ru = *(const float4*)(ubase + (size_t)(toff + ss) * NS + sp);
            rc = *(const float4*)(cbase + (size_t)(toff + ss) * NS + sp);
            rd = *(const float4*)(dbase + (size_t)(toff + ss) * NS + sp);
        }
#pragma unroll
        for (int s = 0; s < TS; s++) {
            float d = sd[cur][s][i];
            float4 ua = *(const float4*)&su[cur][s][4 * g];
            float4 ub = *(const float4*)&su[cur][s][32 + 4 * g];
            float4 ca = *(const float4*)&sc[cur][s][4 * g];
            float4 cb = *(const float4*)&sc[cur][s][32 + 4 * g];
            h[0] = ex2(a[0] * d) * h[0] + ua.x;
            h[1] = ex2(a[1] * d) * h[1] + ua.y;
            h[2] = ex2(a[2] * d) * h[2] + ua.z;
            h[3] = ex2(a[3] * d) * h[3] + ua.w;
            h[4] = ex2(a[4] * d) * h[4] + ub.x;
            h[5] = ex2(a[5] * d) * h[5] + ub.y;
            h[6] = ex2(a[6] * d) * h[6] + ub.z;
            h[7] = ex2(a[7] * d) * h[7] + ub.w;
            float p = ca.x * h[0] + ca.y * h[1] + ca.z * h[2] + ca.w * h[3]
                    + cb.x * h[4] + cb.y * h[5] + cb.z * h[6] + cb.w * h[7];
            p += __shfl_xor_sync(0xffffffffu, p, 4);
            p += __shfl_xor_sync(0xffffffffu, p, 2);
            p += __shfl_xor_sync(0xffffffffu, p, 1);
            if (g == 0) ys[cur][s][iblk] = p;
        }
        if (tile + 1 < NTIL) {
            const int nxt = cur ^ 1;
            *(float4*)&su[nxt][ss][sp] = ru;
            *(float4*)&sc[nxt][ss][sp] = rc;
            *(float4*)&sd[nxt][ss][sp] = rd;
        }
        __syncthreads();
        // coalesced y writeout for this tile
        {
            const int yt = tid >> 4;            // 0..15
            const int yi = (tid & 15) << 1;     // 0..30
            float2 yv = *(const float2*)&ys[cur][yt][yi];
            const int t = t0 + tile * TS + yt;
            *(float2*)&out[((size_t)(b * SQ + t)) * NS + half * 32 + yi] = yv;
        }
    }
}

// --------------------------------- launch -----------------------------------
extern "C" void kernel_launch(void* const* d_in, const int* in_sizes, int n_in,
                              void* d_out, int out_size) {
    const float* x  = (const float*)d_in[0];
    const float* Wd = (const float*)d_in[7];
    const float* bd = (const float*)d_in[8];
    const float* Wb = (const float*)d_in[9];
    const float* bb = (const float*)d_in[10];
    const float* Wc = (const float*)d_in[11];
    const float* bc = (const float*)d_in[12];
    const float* A  = (const float*)d_in[13];
    float* out = (float*)d_out;

    cudaFuncSetAttribute(proj_mma_kernel,
                         cudaFuncAttributeMaxDynamicSharedMemorySize, SMEM_MMA);

    wconv_kernel<<<NTOT * DM / 8 / 256, 256>>>(Wd, Wb, Wc);
    proj_mma_kernel<<<ROWS / MT, 256, SMEM_MMA>>>(x, bd, bb, bc);
    scan1_kernel<<<BQ * GQ * 2, 256>>>(A);
    scan3_kernel<<<BQ * GQ * 2, 256>>>(A, out);
}